// round 9
// baseline (speedup 1.0000x reference)
#include <cuda_runtime.h>
#include <math.h>

#define D_    128
#define N_    16384
#define E_    524288
#define B_    16
#define SEQ_  1024
#define DFF_  512

// ---------------- scratch (device globals: no allocations allowed) ----------
__device__ float g_agg [N_*D_];
__device__ float g_t1  [N_*D_];
__device__ float g_h1  [N_*D_];
__device__ float g_qkv [N_*3*D_];
__device__ float g_attn[N_*D_];
__device__ float g_h2  [N_*D_];
__device__ float g_ffn [N_*DFF_];

// ---------------- helpers ----------------------------------------------------
__device__ __forceinline__ unsigned f2tf(float f){
  unsigned r; asm("cvt.rna.tf32.f32 %0, %1;" : "=r"(r) : "f"(f)); return r;
}
__device__ __forceinline__ void st4tf(float* dst, float4 v){
  unsigned* d = (unsigned*)dst;
  d[0]=f2tf(v.x); d[1]=f2tf(v.y); d[2]=f2tf(v.z); d[3]=f2tf(v.w);
}
// scatter a float4 of 4 consecutive k (c4 multiple of 4, 0..28 within a 32-chunk)
// into pairwise layout: within each 8-group, k-local kl at pos (kl&3)*2 + (kl>>2)
__device__ __forceinline__ void st4tf_pair(unsigned* rowbase, int c4, float4 v){
  int base = ((c4>>3)<<3) + ((c4>>2)&1);
  rowbase[base+0]=f2tf(v.x); rowbase[base+2]=f2tf(v.y);
  rowbase[base+4]=f2tf(v.z); rowbase[base+6]=f2tf(v.w);
}
__device__ __forceinline__ void mma8(float c[4], unsigned a0,unsigned a1,unsigned a2,unsigned a3,
                                     unsigned b0, unsigned b1){
  asm volatile("mma.sync.aligned.m16n8k8.row.col.f32.tf32.tf32.f32 "
      "{%0,%1,%2,%3},{%4,%5,%6,%7},{%8,%9},{%0,%1,%2,%3};"
      : "+f"(c[0]),"+f"(c[1]),"+f"(c[2]),"+f"(c[3])
      : "r"(a0),"r"(a1),"r"(a2),"r"(a3),"r"(b0),"r"(b1));
}
template<int ACT> __device__ __forceinline__ float actf(float x){
  if (ACT==1) return fmaxf(x, 0.f);
  if (ACT==2) return 0.5f*x*(1.f + erff(x*0.70710678118654752f));
  return x;
}

// ---------------- zero init --------------------------------------------------
__global__ void zero_kernel(float4* p, int n){
  int i = blockIdx.x*blockDim.x + threadIdx.x;
  if (i < n) p[i] = make_float4(0.f,0.f,0.f,0.f);
}

// ---------------- fused edge stage -------------------------------------------
// 1024 blocks x 256 threads, 2 CTAs/SM. W resident (4 chunk tiles), A double-
// buffered 32-wide k-chunks, 4 edge tiles of 128 per block.
// e = ea@W^T + b ; msg = relu(h[src]+e) ; red.global.add.v4.f32 scatter
// (lane-paired via shfl to form 16B float4s -> half the atomic op count).
#define EDGE_T 4
#define EDGE_SMEM (6*4608*4 + 512 + 2048)
__global__ void __launch_bounds__(256,2) edge_kernel(
    const float* __restrict__ ea, const float* __restrict__ Wt,
    const float* __restrict__ eb, const float* __restrict__ h,
    const int* __restrict__ src, const int* __restrict__ dst,
    float* __restrict__ agg){
  extern __shared__ unsigned smu[];
  unsigned* Wres = smu;                    // [4][128][36] chunk-major pairwise
  unsigned* Abuf = smu + 4*4608;           // [2][128][36]
  float*    s_eb = (float*)(smu + 6*4608); // [128]
  int*      sidx = (int*)(s_eb + 128);     // [2][256] (src|dst per tile)
  int tid = threadIdx.x;
  // W (128x128) into chunk-major pairwise layout, once per block
  for (int i = tid; i < 4096; i += 256){
    int r = i>>5, c4g = (i&31)<<2;
    float4 w = *(const float4*)(Wt + (size_t)r*128 + c4g);
    st4tf_pair(Wres + (c4g>>5)*4608 + r*36, c4g&31, w);
  }
  if (tid < 128) s_eb[tid] = eb[tid];
  int c4 = (tid&7)<<2;
  int rl[4];
  #pragma unroll
  for (int it=0; it<4; it++) rl[it] = (tid + it*256)>>3;
  // prologue: tile0 indices + chunk0 into buf0
  {
    int e0 = blockIdx.x*(EDGE_T*128);
    sidx[tid] = (tid<128) ? src[e0+tid] : dst[e0+tid-128];
    #pragma unroll
    for (int it=0; it<4; it++){
      float4 v = *(const float4*)(ea + (size_t)(e0+rl[it])*128 + c4);
      st4tf_pair(Abuf + rl[it]*36, c4, v);
    }
  }
  int warp = tid>>5, lane = tid&31, gr = lane>>2, tg = lane&3;
  int wm = warp>>1, wn = warp&1;   // rows wm*32+, cols wn*64+
  float acc[2][8][4];
  #pragma unroll
  for (int mt=0;mt<2;mt++)
    #pragma unroll
    for (int nt=0;nt<8;nt++){acc[mt][nt][0]=acc[mt][nt][1]=acc[mt][nt][2]=acc[mt][nt][3]=0.f;}
  float4 va[4]; int idxreg = 0;
  const int NIT = EDGE_T*4;
  for (int i = 0; i < NIT; i++){
    __syncthreads();
    int ip = i+1;
    if (ip < NIT){
      int t_ = ip>>2, c_ = ip&3;
      int e0 = blockIdx.x*(EDGE_T*128) + t_*128;
      #pragma unroll
      for (int it=0; it<4; it++)
        va[it] = *(const float4*)(ea + (size_t)(e0+rl[it])*128 + c_*32 + c4);
      if (c_ == 0) idxreg = (tid<128) ? src[e0+tid] : dst[e0+tid-128];
    }
    const unsigned* Ab = Abuf + (i&1)*4608;
    const unsigned* Wb = Wres + (i&3)*4608;
    #pragma unroll
    for (int ks=0; ks<4; ks++){
      uint2 alo0 = *(const uint2*)(Ab + (wm*32+   gr)*36 + ks*8 + tg*2);
      uint2 ahi0 = *(const uint2*)(Ab + (wm*32+ 8+gr)*36 + ks*8 + tg*2);
      uint2 alo1 = *(const uint2*)(Ab + (wm*32+16+gr)*36 + ks*8 + tg*2);
      uint2 ahi1 = *(const uint2*)(Ab + (wm*32+24+gr)*36 + ks*8 + tg*2);
      #pragma unroll
      for (int nt=0;nt<8;nt++){
        uint2 bb = *(const uint2*)(Wb + (wn*64+nt*8+gr)*36 + ks*8 + tg*2);
        mma8(acc[0][nt], alo0.x, ahi0.x, alo0.y, ahi0.y, bb.x, bb.y);
        mma8(acc[1][nt], alo1.x, ahi1.x, alo1.y, ahi1.y, bb.x, bb.y);
      }
    }
    if (ip < NIT){
      unsigned* Ad = Abuf + (ip&1)*4608;
      #pragma unroll
      for (int it=0; it<4; it++) st4tf_pair(Ad + rl[it]*36, c4, va[it]);
      if ((ip&3)==0) sidx[((ip>>2)&1)*256 + tid] = idxreg;
    }
    if ((i&3)==3){
      int tp = ((i>>2)&1)*256;
      #pragma unroll
      for (int mt=0;mt<2;mt++){
        #pragma unroll
        for (int half=0; half<2; half++){
          int r = wm*32 + mt*16 + half*8 + gr;
          int sid = sidx[tp+r], did = sidx[tp+128+r];
          const float* hrow = h   + (size_t)sid*128;
          float*       arow = agg + (size_t)did*128;
          #pragma unroll
          for (int nt=0;nt<8;nt++){
            int col = wn*64 + nt*8 + 2*tg;
            float2 hv = *(const float2*)(hrow + col);
            float v0 = fmaxf(acc[mt][nt][half*2+0] + s_eb[col]   + hv.x, 0.f);
            float v1 = fmaxf(acc[mt][nt][half*2+1] + s_eb[col+1] + hv.y, 0.f);
            // pair lanes tg<->tg^1 to assemble 4 consecutive cols, then one
            // red.v4 per pair (issuer alternates with nt parity)
            unsigned long long pk;
            asm("mov.b64 %0, {%1,%2};" : "=l"(pk) : "f"(v0), "f"(v1));
            unsigned long long qk = __shfl_xor_sync(0xffffffffu, pk, 1);
            float q0, q1;
            asm("mov.b64 {%0,%1}, %2;" : "=f"(q0), "=f"(q1) : "l"(qk));
            if (((tg ^ nt) & 1) == 0){
              int cbase = wn*64 + nt*8 + ((tg&2)<<1);
              float a0,a1,a2,a3;
              if ((tg&1)==0){ a0=v0; a1=v1; a2=q0; a3=q1; }
              else          { a0=q0; a1=q1; a2=v0; a3=v1; }
              asm volatile("red.global.add.v4.f32 [%0], {%1,%2,%3,%4};"
                  :: "l"(arow + cbase), "f"(a0),"f"(a1),"f"(a2),"f"(a3) : "memory");
            }
          }
        }
      }
      #pragma unroll
      for (int mt=0;mt<2;mt++)
        #pragma unroll
        for (int nt=0;nt<8;nt++){acc[mt][nt][0]=acc[mt][nt][1]=acc[mt][nt][2]=acc[mt][nt][3]=0.f;}
    }
  }
}

// ---------------- generic tf32 GEMM: C = act(A(+A2)@W^T + bias) --------------
// block: 128 threads, tile 64(M) x 128(N), double-buffered 32-wide k-chunks.
// LNM: 0 = plain store; 1 = C[row] = LN(R[row] + out); 2 = orow=midx[row],
//      C[orow] = LN(R[orow] + out).  (LNM requires Nout==128, grid.x==1.)
#define GEMM_SMEM ((2*64*36 + 2*128*36)*4)
template<int ACT, bool HASA2, bool GATHER, int LNM>
__global__ void __launch_bounds__(128,3) gemm_kernel(
    const float* __restrict__ A, const float* __restrict__ A2,
    const int* __restrict__ gidx, const float* __restrict__ W,
    const float* __restrict__ bias, float* __restrict__ C,
    int K, int Nout,
    const float* __restrict__ Rres, const int* __restrict__ midx,
    const float* __restrict__ lnw, const float* __restrict__ lnb){
  extern __shared__ float sm[];
  unsigned* Asm = (unsigned*)sm;             // [2][64*36]
  unsigned* Wsm = (unsigned*)(sm + 2*64*36); // [2][128*36]
  int tid = threadIdx.x, warp = tid>>5, lane = tid&31, gr = lane>>2, tg = lane&3;
  int wm = warp>>1, wn = warp&1;
  int m0 = blockIdx.y*64, n0 = blockIdx.x*128;
  int c4 = (tid&7)<<2;
  int abase = ((c4>>3)<<3) + ((c4>>2)&1);
  int lrow[4], arow[4], wrow[8];
  #pragma unroll
  for (int it=0; it<4; it++){
    int r = (tid + it*128)>>3;
    lrow[it] = m0 + r;
    arow[it] = GATHER ? gidx[m0+r] : (m0+r);
  }
  #pragma unroll
  for (int it=0; it<8; it++) wrow[it] = n0 + ((tid + it*128)>>3);

  float4 va[4], vw[8];
  #pragma unroll
  for (int it=0; it<4; it++){
    va[it] = *(const float4*)(A + (size_t)arow[it]*K + c4);
    if (HASA2){
      float4 u = *(const float4*)(A2 + (size_t)lrow[it]*K + c4);
      va[it].x+=u.x; va[it].y+=u.y; va[it].z+=u.z; va[it].w+=u.w;
    }
  }
  #pragma unroll
  for (int it=0; it<8; it++) vw[it] = *(const float4*)(W + (size_t)wrow[it]*K + c4);
  #pragma unroll
  for (int it=0; it<4; it++){
    unsigned* d = Asm + ((tid+it*128)>>3)*36 + abase;
    d[0]=f2tf(va[it].x); d[2]=f2tf(va[it].y); d[4]=f2tf(va[it].z); d[6]=f2tf(va[it].w);
  }
  #pragma unroll
  for (int it=0; it<8; it++){
    unsigned* d = Wsm + ((tid+it*128)>>3)*36 + abase;
    d[0]=f2tf(vw[it].x); d[2]=f2tf(vw[it].y); d[4]=f2tf(vw[it].z); d[6]=f2tf(vw[it].w);
  }

  float acc[2][8][4];
  #pragma unroll
  for (int mt=0;mt<2;mt++)
    #pragma unroll
    for (int nt=0;nt<8;nt++){acc[mt][nt][0]=acc[mt][nt][1]=acc[mt][nt][2]=acc[mt][nt][3]=0.f;}

  int nc = K >> 5;
  for (int c = 0; c < nc; c++){
    __syncthreads();
    if (c+1 < nc){
      int k0 = (c+1)<<5;
      #pragma unroll
      for (int it=0; it<4; it++){
        va[it] = *(const float4*)(A + (size_t)arow[it]*K + k0 + c4);
        if (HASA2){
          float4 u = *(const float4*)(A2 + (size_t)lrow[it]*K + k0 + c4);
          va[it].x+=u.x; va[it].y+=u.y; va[it].z+=u.z; va[it].w+=u.w;
        }
      }
      #pragma unroll
      for (int it=0; it<8; it++) vw[it] = *(const float4*)(W + (size_t)wrow[it]*K + k0 + c4);
    }
    const unsigned* Ab = Asm + (c&1)*64*36;
    const unsigned* Wb = Wsm + (c&1)*128*36;
    #pragma unroll
    for (int ks=0; ks<4; ks++){
      uint2 alo0 = *(const uint2*)(Ab + (wm*32+   gr)*36 + ks*8 + tg*2);
      uint2 ahi0 = *(const uint2*)(Ab + (wm*32+ 8+gr)*36 + ks*8 + tg*2);
      uint2 alo1 = *(const uint2*)(Ab + (wm*32+16+gr)*36 + ks*8 + tg*2);
      uint2 ahi1 = *(const uint2*)(Ab + (wm*32+24+gr)*36 + ks*8 + tg*2);
      #pragma unroll
      for (int nt=0;nt<8;nt++){
        uint2 bb = *(const uint2*)(Wb + (wn*64+nt*8+gr)*36 + ks*8 + tg*2);
        mma8(acc[0][nt], alo0.x, ahi0.x, alo0.y, ahi0.y, bb.x, bb.y);
        mma8(acc[1][nt], alo1.x, ahi1.x, alo1.y, ahi1.y, bb.x, bb.y);
      }
    }
    if (c+1 < nc){
      unsigned* Ad = Asm + ((c+1)&1)*64*36;
      unsigned* Wd = Wsm + ((c+1)&1)*128*36;
      #pragma unroll
      for (int it=0; it<4; it++){
        unsigned* d = Ad + ((tid+it*128)>>3)*36 + abase;
        d[0]=f2tf(va[it].x); d[2]=f2tf(va[it].y); d[4]=f2tf(va[it].z); d[6]=f2tf(va[it].w);
      }
      #pragma unroll
      for (int it=0; it<8; it++){
        unsigned* d = Wd + ((tid+it*128)>>3)*36 + abase;
        d[0]=f2tf(vw[it].x); d[2]=f2tf(vw[it].y); d[4]=f2tf(vw[it].z); d[6]=f2tf(vw[it].w);
      }
    }
  }

  if (LNM == 0){
    #pragma unroll
    for (int mt=0;mt<2;mt++){
      #pragma unroll
      for (int nt=0;nt<8;nt++){
        int row = m0 + wm*32 + mt*16 + gr;
        int col = n0 + wn*64 + nt*8 + 2*tg;
        float2 bv = *(const float2*)(bias + col);
        float v00 = actf<ACT>(acc[mt][nt][0] + bv.x);
        float v01 = actf<ACT>(acc[mt][nt][1] + bv.y);
        float v10 = actf<ACT>(acc[mt][nt][2] + bv.x);
        float v11 = actf<ACT>(acc[mt][nt][3] + bv.y);
        *(float2*)(C + (size_t)row*Nout + col)     = make_float2(v00, v01);
        *(float2*)(C + (size_t)(row+8)*Nout + col) = make_float2(v10, v11);
      }
    }
  } else {
    // fused LayerNorm epilogue over full 128-col rows
    __syncthreads();
    float2* red = (float2*)sm;   // [64][2]
    int orows[2][2];
    #pragma unroll
    for (int mt=0;mt<2;mt++){
      #pragma unroll
      for (int half=0; half<2; half++){
        int rl_ = wm*32 + mt*16 + half*8 + gr;
        int row = m0 + rl_;
        int orow = (LNM==2) ? midx[row] : row;
        orows[mt][half] = orow;
        const float* R = Rres + (size_t)orow*128;
        float s = 0.f, q = 0.f;
        #pragma unroll
        for (int nt=0;nt<8;nt++){
          int col = wn*64 + nt*8 + 2*tg;
          float2 bv = *(const float2*)(bias + col);
          float2 rv = *(const float2*)(R + col);
          float v0 = acc[mt][nt][half*2+0] + bv.x + rv.x;
          float v1 = acc[mt][nt][half*2+1] + bv.y + rv.y;
          acc[mt][nt][half*2+0] = v0; acc[mt][nt][half*2+1] = v1;
          s += v0 + v1; q += v0*v0 + v1*v1;
        }
        s += __shfl_xor_sync(0xffffffffu, s, 1); q += __shfl_xor_sync(0xffffffffu, q, 1);
        s += __shfl_xor_sync(0xffffffffu, s, 2); q += __shfl_xor_sync(0xffffffffu, q, 2);
        if (tg == 0) red[rl_*2 + wn] = make_float2(s, q);
      }
    }
    __syncthreads();
    #pragma unroll
    for (int mt=0;mt<2;mt++){
      #pragma unroll
      for (int half=0; half<2; half++){
        int rl_ = wm*32 + mt*16 + half*8 + gr;
        float2 p0 = red[rl_*2], p1 = red[rl_*2+1];
        float S = p0.x + p1.x, Q = p0.y + p1.y;
        float mu = S*(1.f/128.f);
        float var = Q*(1.f/128.f) - mu*mu;
        float rs = rsqrtf(var + 1e-5f);
        float* Co = C + (size_t)orows[mt][half]*128;
        #pragma unroll
        for (int nt=0;nt<8;nt++){
          int col = wn*64 + nt*8 + 2*tg;
          float2 wv = *(const float2*)(lnw + col);
          float2 bv = *(const float2*)(lnb + col);
          float o0 = (acc[mt][nt][half*2+0]-mu)*rs*wv.x + bv.x;
          float o1 = (acc[mt][nt][half*2+1]-mu)*rs*wv.y + bv.y;
          *(float2*)(Co + col) = make_float2(o0, o1);
        }
      }
    }
  }
}

// ---------------- flash attention v2 ------------------------------------------
// K-tile 64, double-buffered K/V, 2 CTAs/SM. No mask (every graph = 1024 nodes).
#define ATTN_SMEM ((128*20 + 2*64*20 + 2*64*24 + 128*68)*4)
__global__ void __launch_bounds__(256,2) attn_kernel(const float* __restrict__ qkv,
                                                     float* __restrict__ outp){
  extern __shared__ float sm[];
  float* Qs = sm;                 // [128][20]     pairwise k layout
  float* Ks = sm + 2560;          // [2][64][20]   pairwise k layout
  float* Vs = sm + 5120;          // [2][64][24]   plain layout
  float* Ps = sm + 8192;          // [128][68]     pairwise k layout
  const unsigned* Qu = (const unsigned*)Qs;
  unsigned*       Pu = (unsigned*)Ps;
  int tid = threadIdx.x, warp = tid>>5, lane = tid&31, gr = lane>>2, tg = lane&3;
  int qt = blockIdx.x, bh = blockIdx.y;
  int b = bh>>3, hh = bh&7;
  int qrow0 = b*SEQ_ + qt*128;
  for (int i = tid; i < 512; i += 256){
    int r = i>>2, c4 = (i&3)<<2;
    float4 v = *(const float4*)(qkv + (size_t)(qrow0+r)*384 + hh*16 + c4);
    v.x*=0.25f; v.y*=0.25f; v.z*=0.25f; v.w*=0.25f;   // 1/sqrt(hd)
    st4tf_pair((unsigned*)Qs + r*20, c4, v);
  }
  int rr = tid>>2, cc4 = (tid&3)<<2;   // per-thread K/V load coords (64 rows x 4 f4)
  // prologue: KV tile 0 into buffer 0
  {
    int kr = b*SEQ_ + rr;
    float4 kk = *(const float4*)(qkv + (size_t)kr*384 + 128 + hh*16 + cc4);
    st4tf_pair((unsigned*)Ks + rr*20, cc4, kk);
    float4 vv = *(const float4*)(qkv + (size_t)kr*384 + 256 + hh*16 + cc4);
    st4tf(Vs + rr*24 + cc4, vv);
  }
  int m0 = warp*16;
  int p0 = ((2*tg)&3)*2 + (tg>>1);
  int p1 = ((2*tg+1)&3)*2 + (tg>>1);
  float mrow0 = -1e30f, mrow1 = -1e30f, lrow0 = 0.f, lrow1 = 0.f;
  float o[2][4];
  #pragma unroll
  for (int nt=0;nt<2;nt++){o[nt][0]=o[nt][1]=o[nt][2]=o[nt][3]=0.f;}

  for (int kt = 0; kt < 16; kt++){
    __syncthreads();
    float4 kk, vv;
    if (kt+1 < 16){
      int kr = b*SEQ_ + (kt+1)*64 + rr;
      kk = *(const float4*)(qkv + (size_t)kr*384 + 128 + hh*16 + cc4);
      vv = *(const float4*)(qkv + (size_t)kr*384 + 256 + hh*16 + cc4);
    }
    const unsigned* Kb = (const unsigned*)Ks + (kt&1)*1280;
    const unsigned* Vb = (const unsigned*)Vs + (kt&1)*1536;
    float s[8][4];
    #pragma unroll
    for (int j=0;j<8;j++){s[j][0]=s[j][1]=s[j][2]=s[j][3]=0.f;}
    #pragma unroll
    for (int ks=0; ks<2; ks++){
      uint2 alo = *(const uint2*)(Qu + (m0+gr  )*20 + ks*8 + tg*2);
      uint2 ahi = *(const uint2*)(Qu + (m0+gr+8)*20 + ks*8 + tg*2);
      #pragma unroll
      for (int j=0;j<8;j++){
        uint2 bb = *(const uint2*)(Kb + (j*8+gr)*20 + ks*8 + tg*2);
        mma8(s[j], alo.x, ahi.x, alo.y, ahi.y, bb.x, bb.y);
      }
    }
    // online softmax: rows gr (comps 0,1) and gr+8 (comps 2,3)
    float mx0 = -1e30f, mx1 = -1e30f;
    #pragma unroll
    for (int j=0;j<8;j++){
      mx0 = fmaxf(mx0, fmaxf(s[j][0], s[j][1]));
      mx1 = fmaxf(mx1, fmaxf(s[j][2], s[j][3]));
    }
    mx0 = fmaxf(mx0, __shfl_xor_sync(0xffffffffu, mx0, 1));
    mx0 = fmaxf(mx0, __shfl_xor_sync(0xffffffffu, mx0, 2));
    mx1 = fmaxf(mx1, __shfl_xor_sync(0xffffffffu, mx1, 1));
    mx1 = fmaxf(mx1, __shfl_xor_sync(0xffffffffu, mx1, 2));
    float mn0 = fmaxf(mrow0, mx0), mn1 = fmaxf(mrow1, mx1);
    float al0 = __expf(mrow0 - mn0), al1 = __expf(mrow1 - mn1);
    mrow0 = mn0; mrow1 = mn1;
    float ls0 = 0.f, ls1 = 0.f;
    #pragma unroll
    for (int j=0;j<8;j++){
      s[j][0] = __expf(s[j][0]-mn0); s[j][1] = __expf(s[j][1]-mn0);
      s[j][2] = __expf(s[j][2]-mn1); s[j][3] = __expf(s[j][3]-mn1);
      ls0 += s[j][0]+s[j][1]; ls1 += s[j][2]+s[j][3];
    }
    ls0 += __shfl_xor_sync(0xffffffffu, ls0, 1); ls0 += __shfl_xor_sync(0xffffffffu, ls0, 2);
    ls1 += __shfl_xor_sync(0xffffffffu, ls1, 1); ls1 += __shfl_xor_sync(0xffffffffu, ls1, 2);
    lrow0 = lrow0*al0 + ls0; lrow1 = lrow1*al1 + ls1;
    #pragma unroll
    for (int nt=0;nt<2;nt++){ o[nt][0]*=al0; o[nt][1]*=al0; o[nt][2]*=al1; o[nt][3]*=al1; }
    #pragma unroll
    for (int j=0;j<8;j++){
      Pu[(m0+gr  )*68 + j*8 + p0] = f2tf(s[j][0]);
      Pu[(m0+gr  )*68 + j*8 + p1] = f2tf(s[j][1]);
      Pu[(m0+gr+8)*68 + j*8 + p0] = f2tf(s[j][2]);
      Pu[(m0+gr+8)*68 + j*8 + p1] = f2tf(s[j][3]);
    }
    __syncwarp();
    #pragma unroll
    for (int ks=0; ks<8; ks++){
      uint2 alo = *(const uint2*)(Pu + (m0+gr  )*68 + ks*8 + tg*2);
      uint2 ahi = *(const uint2*)(Pu + (m0+gr+8)*68 + ks*8 + tg*2);
      #pragma unroll
      for (int nt=0; nt<2; nt++){
        unsigned b0 = Vb[(ks*8+tg  )*24 + nt*8 + gr];
        unsigned b1 = Vb[(ks*8+tg+4)*24 + nt*8 + gr];
        mma8(o[nt], alo.x, ahi.x, alo.y, ahi.y, b0, b1);
      }
    }
    if (kt+1 < 16){
      st4tf_pair((unsigned*)Ks + ((kt+1)&1)*1280 + rr*20, cc4, kk);
      st4tf(Vs + ((kt+1)&1)*1536 + rr*24 + cc4, vv);
    }
  }
  float inv0 = 1.f/lrow0, inv1 = 1.f/lrow1;
  #pragma unroll
  for (int nt=0; nt<2; nt++){
    int col = hh*16 + nt*8 + 2*tg;
    size_t r0 = (size_t)(qrow0 + m0 + gr    )*128 + col;
    size_t r1 = (size_t)(qrow0 + m0 + gr + 8)*128 + col;
    *(float2*)(outp + r0) = make_float2(o[nt][0]*inv0, o[nt][1]*inv0);
    *(float2*)(outp + r1) = make_float2(o[nt][2]*inv1, o[nt][3]*inv1);
  }
}

// ---------------- launch ------------------------------------------------------
extern "C" void kernel_launch(void* const* d_in, const int* in_sizes, int n_in,
                              void* d_out, int out_size){
  const float* h         = (const float*)d_in[0];
  const float* edge_attr = (const float*)d_in[1];
  const float* edge_w    = (const float*)d_in[2];
  const float* edge_b    = (const float*)d_in[3];
  const float* gin_w1    = (const float*)d_in[4];
  const float* gin_b1    = (const float*)d_in[5];
  const float* gin_w2    = (const float*)d_in[6];
  const float* gin_b2    = (const float*)d_in[7];
  const float* in_proj_w = (const float*)d_in[8];
  const float* in_proj_b = (const float*)d_in[9];
  const float* out_w     = (const float*)d_in[10];
  const float* out_b     = (const float*)d_in[11];
  const float* ffn_w1    = (const float*)d_in[12];
  const float* ffn_b1    = (const float*)d_in[13];
  const float* ffn_w2    = (const float*)d_in[14];
  const float* ffn_b2    = (const float*)d_in[15];
  const float* ln1_w     = (const float*)d_in[16];
  const float* ln1_b     = (const float*)d_in[17];
  const float* ln2_w     = (const float*)d_in[18];
  const float* ln2_b     = (const float*)d_in[19];
  const float* ln3_w     = (const float*)d_in[20];
  const float* ln3_b     = (const float*)d_in[21];
  const int*   edge_index= (const int*)d_in[22];
  const int*   sort_idx  = (const int*)d_in[24];
  float* outp = (float*)d_out;

  float *agg,*t1,*h1b,*qkvb,*attnb,*h2b,*ffnb;
  cudaGetSymbolAddress((void**)&agg,  g_agg);
  cudaGetSymbolAddress((void**)&t1,   g_t1);
  cudaGetSymbolAddress((void**)&h1b,  g_h1);
  cudaGetSymbolAddress((void**)&qkvb, g_qkv);
  cudaGetSymbolAddress((void**)&attnb,g_attn);
  cudaGetSymbolAddress((void**)&h2b,  g_h2);
  cudaGetSymbolAddress((void**)&ffnb, g_ffn);

  cudaFuncSetAttribute(edge_kernel, cudaFuncAttributeMaxDynamicSharedMemorySize, EDGE_SMEM);
  cudaFuncSetAttribute(gemm_kernel<1,true ,false,0>, cudaFuncAttributeMaxDynamicSharedMemorySize, GEMM_SMEM);
  cudaFuncSetAttribute(gemm_kernel<0,false,false,1>, cudaFuncAttributeMaxDynamicSharedMemorySize, GEMM_SMEM);
  cudaFuncSetAttribute(gemm_kernel<0,false,true ,0>, cudaFuncAttributeMaxDynamicSharedMemorySize, GEMM_SMEM);
  cudaFuncSetAttribute(gemm_kernel<0,false,false,2>, cudaFuncAttributeMaxDynamicSharedMemorySize, GEMM_SMEM);
  cudaFuncSetAttribute(gemm_kernel<2,false,false,0>, cudaFuncAttributeMaxDynamicSharedMemorySize, GEMM_SMEM);
  cudaFuncSetAttribute(attn_kernel, cudaFuncAttributeMaxDynamicSharedMemorySize, ATTN_SMEM);

  // 1) agg = 0
  zero_kernel<<<(N_*D_/4 + 255)/256, 256>>>((float4*)agg, N_*D_/4);
  // 2) fused GINE edge stage
  edge_kernel<<<E_/(EDGE_T*128), 256, EDGE_SMEM>>>(edge_attr, edge_w, edge_b, h,
                                                   edge_index, edge_index + E_, agg);
  // 3) gin MLP: t1 = relu((h+agg)@w1^T+b1) ; h1 = LN1(h + t1@w2^T+b2)   [LN fused]
  gemm_kernel<1,true ,false,0><<<dim3(1,N_/64),128,GEMM_SMEM>>>(h,  agg,    nullptr, gin_w1, gin_b1, t1,  128, 128, nullptr, nullptr, nullptr, nullptr);
  gemm_kernel<0,false,false,1><<<dim3(1,N_/64),128,GEMM_SMEM>>>(t1, nullptr,nullptr, gin_w2, gin_b2, h1b, 128, 128, h, nullptr, ln1_w, ln1_b);
  // 4) qkv (gathered by sort_idx into dense order)
  gemm_kernel<0,false,true ,0><<<dim3(3,N_/64),128,GEMM_SMEM>>>(h, nullptr, sort_idx, in_proj_w, in_proj_b, qkvb, 128, 384, nullptr, nullptr, nullptr, nullptr);
  // 5) attention (full softmax, all graphs exactly 1024 nodes)
  attn_kernel<<<dim3(8,128),256,ATTN_SMEM>>>(qkvb, attnb);
  // 6) out projection + fused LN2 with unsort scatter: h2[sort_idx[j]] = LN(h1[sort_idx[j]] + ao_j)
  gemm_kernel<0,false,false,2><<<dim3(1,N_/64),128,GEMM_SMEM>>>(attnb, nullptr,nullptr, out_w, out_b, h2b, 128, 128, h1b, sort_idx, ln2_w, ln2_b);
  // 7) FFN: gelu gemm, then ffn2 + fused LN3 -> final output
  gemm_kernel<2,false,false,0><<<dim3(4,N_/64),128,GEMM_SMEM>>>(h2b, nullptr,nullptr, ffn_w1, ffn_b1, ffnb, 128, 512, nullptr, nullptr, nullptr, nullptr);
  gemm_kernel<0,false,false,1><<<dim3(1,N_/64),128,GEMM_SMEM>>>(ffnb,nullptr,nullptr, ffn_w2, ffn_b2, outp, 512, 128, h2b, nullptr, ln3_w, ln3_b);
}

// round 11
// speedup vs baseline: 1.0534x; 1.0534x over previous
#include <cuda_runtime.h>
#include <math.h>

#define D_    128
#define N_    16384
#define E_    524288
#define B_    16
#define SEQ_  1024
#define DFF_  512

// ---------------- scratch (device globals: no allocations allowed) ----------
__device__ float g_agg [N_*D_];
__device__ float g_t1  [N_*D_];
__device__ float g_h1  [N_*D_];
__device__ float g_qkv [N_*3*D_];
__device__ float g_attn[N_*D_];
__device__ float g_h2  [N_*D_];
__device__ float g_ffn [N_*DFF_];

// ---------------- streams/events for branch overlap (created once at load) ---
struct StreamHolder {
  cudaStream_t s2; cudaEvent_t evFork, evJoin;
  StreamHolder(){
    cudaStreamCreateWithFlags(&s2, cudaStreamNonBlocking);
    cudaEventCreateWithFlags(&evFork, cudaEventDisableTiming);
    cudaEventCreateWithFlags(&evJoin, cudaEventDisableTiming);
  }
};
static StreamHolder g_sh;

// ---------------- helpers ----------------------------------------------------
__device__ __forceinline__ unsigned f2tf(float f){
  unsigned r; asm("cvt.rna.tf32.f32 %0, %1;" : "=r"(r) : "f"(f)); return r;
}
__device__ __forceinline__ void st4tf(float* dst, float4 v){
  unsigned* d = (unsigned*)dst;
  d[0]=f2tf(v.x); d[1]=f2tf(v.y); d[2]=f2tf(v.z); d[3]=f2tf(v.w);
}
// scatter a float4 of 4 consecutive k (c4 multiple of 4, 0..28 within a 32-chunk)
// into pairwise layout: within each 8-group, k-local kl at pos (kl&3)*2 + (kl>>2)
__device__ __forceinline__ void st4tf_pair(unsigned* rowbase, int c4, float4 v){
  int base = ((c4>>3)<<3) + ((c4>>2)&1);
  rowbase[base+0]=f2tf(v.x); rowbase[base+2]=f2tf(v.y);
  rowbase[base+4]=f2tf(v.z); rowbase[base+6]=f2tf(v.w);
}
__device__ __forceinline__ void mma8(float c[4], unsigned a0,unsigned a1,unsigned a2,unsigned a3,
                                     unsigned b0, unsigned b1){
  asm volatile("mma.sync.aligned.m16n8k8.row.col.f32.tf32.tf32.f32 "
      "{%0,%1,%2,%3},{%4,%5,%6,%7},{%8,%9},{%0,%1,%2,%3};"
      : "+f"(c[0]),"+f"(c[1]),"+f"(c[2]),"+f"(c[3])
      : "r"(a0),"r"(a1),"r"(a2),"r"(a3),"r"(b0),"r"(b1));
}
template<int ACT> __device__ __forceinline__ float actf(float x){
  if (ACT==1) return fmaxf(x, 0.f);
  if (ACT==2) return 0.5f*x*(1.f + erff(x*0.70710678118654752f));
  return x;
}

// ---------------- zero init --------------------------------------------------
__global__ void zero_kernel(float4* p, int n){
  int i = blockIdx.x*blockDim.x + threadIdx.x;
  if (i < n) p[i] = make_float4(0.f,0.f,0.f,0.f);
}

// ---------------- fused edge stage -------------------------------------------
// 1024 blocks x 256 threads, 2 CTAs/SM. W resident (4 chunk tiles), A double-
// buffered 32-wide k-chunks, 4 edge tiles of 128 per block.
// e = ea@W^T + b ; msg = relu(h[src]+e) ; atomicAdd(float2) scatter.
#define EDGE_T 4
#define EDGE_SMEM (6*4608*4 + 512 + 2048)
__global__ void __launch_bounds__(256,2) edge_kernel(
    const float* __restrict__ ea, const float* __restrict__ Wt,
    const float* __restrict__ eb, const float* __restrict__ h,
    const int* __restrict__ src, const int* __restrict__ dst,
    float* __restrict__ agg){
  extern __shared__ unsigned smu[];
  unsigned* Wres = smu;                    // [4][128][36] chunk-major pairwise
  unsigned* Abuf = smu + 4*4608;           // [2][128][36]
  float*    s_eb = (float*)(smu + 6*4608); // [128]
  int*      sidx = (int*)(s_eb + 128);     // [2][256] (src|dst per tile)
  int tid = threadIdx.x;
  // W (128x128) into chunk-major pairwise layout, once per block
  for (int i = tid; i < 4096; i += 256){
    int r = i>>5, c4g = (i&31)<<2;
    float4 w = *(const float4*)(Wt + (size_t)r*128 + c4g);
    st4tf_pair(Wres + (c4g>>5)*4608 + r*36, c4g&31, w);
  }
  if (tid < 128) s_eb[tid] = eb[tid];
  int c4 = (tid&7)<<2;
  int rl[4];
  #pragma unroll
  for (int it=0; it<4; it++) rl[it] = (tid + it*256)>>3;
  // prologue: tile0 indices + chunk0 into buf0
  {
    int e0 = blockIdx.x*(EDGE_T*128);
    sidx[tid] = (tid<128) ? src[e0+tid] : dst[e0+tid-128];
    #pragma unroll
    for (int it=0; it<4; it++){
      float4 v = *(const float4*)(ea + (size_t)(e0+rl[it])*128 + c4);
      st4tf_pair(Abuf + rl[it]*36, c4, v);
    }
  }
  int warp = tid>>5, lane = tid&31, gr = lane>>2, tg = lane&3;
  int wm = warp>>1, wn = warp&1;   // rows wm*32+, cols wn*64+
  float acc[2][8][4];
  #pragma unroll
  for (int mt=0;mt<2;mt++)
    #pragma unroll
    for (int nt=0;nt<8;nt++){acc[mt][nt][0]=acc[mt][nt][1]=acc[mt][nt][2]=acc[mt][nt][3]=0.f;}
  float4 va[4]; int idxreg = 0;
  const int NIT = EDGE_T*4;
  for (int i = 0; i < NIT; i++){
    __syncthreads();
    int ip = i+1;
    if (ip < NIT){
      int t_ = ip>>2, c_ = ip&3;
      int e0 = blockIdx.x*(EDGE_T*128) + t_*128;
      #pragma unroll
      for (int it=0; it<4; it++)
        va[it] = *(const float4*)(ea + (size_t)(e0+rl[it])*128 + c_*32 + c4);
      if (c_ == 0) idxreg = (tid<128) ? src[e0+tid] : dst[e0+tid-128];
    }
    const unsigned* Ab = Abuf + (i&1)*4608;
    const unsigned* Wb = Wres + (i&3)*4608;
    #pragma unroll
    for (int ks=0; ks<4; ks++){
      uint2 alo0 = *(const uint2*)(Ab + (wm*32+   gr)*36 + ks*8 + tg*2);
      uint2 ahi0 = *(const uint2*)(Ab + (wm*32+ 8+gr)*36 + ks*8 + tg*2);
      uint2 alo1 = *(const uint2*)(Ab + (wm*32+16+gr)*36 + ks*8 + tg*2);
      uint2 ahi1 = *(const uint2*)(Ab + (wm*32+24+gr)*36 + ks*8 + tg*2);
      #pragma unroll
      for (int nt=0;nt<8;nt++){
        uint2 bb = *(const uint2*)(Wb + (wn*64+nt*8+gr)*36 + ks*8 + tg*2);
        mma8(acc[0][nt], alo0.x, ahi0.x, alo0.y, ahi0.y, bb.x, bb.y);
        mma8(acc[1][nt], alo1.x, ahi1.x, alo1.y, ahi1.y, bb.x, bb.y);
      }
    }
    if (ip < NIT){
      unsigned* Ad = Abuf + (ip&1)*4608;
      #pragma unroll
      for (int it=0; it<4; it++) st4tf_pair(Ad + rl[it]*36, c4, va[it]);
      if ((ip&3)==0) sidx[((ip>>2)&1)*256 + tid] = idxreg;
    }
    if ((i&3)==3){
      int tp = ((i>>2)&1)*256;
      #pragma unroll
      for (int mt=0;mt<2;mt++){
        #pragma unroll
        for (int half=0; half<2; half++){
          int r = wm*32 + mt*16 + half*8 + gr;
          int sid = sidx[tp+r], did = sidx[tp+128+r];
          const float* hrow = h   + (size_t)sid*128;
          float*       arow = agg + (size_t)did*128;
          #pragma unroll
          for (int nt=0;nt<8;nt++){
            int col = wn*64 + nt*8 + 2*tg;
            float2 hv = *(const float2*)(hrow + col);
            float v0 = acc[mt][nt][half*2+0] + s_eb[col]   + hv.x;
            float v1 = acc[mt][nt][half*2+1] + s_eb[col+1] + hv.y;
            atomicAdd((float2*)(arow + col), make_float2(fmaxf(v0,0.f), fmaxf(v1,0.f)));
          }
        }
      }
      #pragma unroll
      for (int mt=0;mt<2;mt++)
        #pragma unroll
        for (int nt=0;nt<8;nt++){acc[mt][nt][0]=acc[mt][nt][1]=acc[mt][nt][2]=acc[mt][nt][3]=0.f;}
    }
  }
}

// ---------------- generic tf32 GEMM: C = act(A(+A2)@W^T + bias) --------------
// block: 128 threads, tile 64(M) x 128(N), double-buffered 32-wide k-chunks.
// LNM: 0 = plain store; 1 = C[row] = LN(R[row] + out); 2 = orow=midx[row],
//      C[orow] = LN(R[orow] + out).  (LNM requires Nout==128, grid.x==1.)
#define GEMM_SMEM ((2*64*36 + 2*128*36)*4)
template<int ACT, bool HASA2, bool GATHER, int LNM>
__global__ void __launch_bounds__(128,3) gemm_kernel(
    const float* __restrict__ A, const float* __restrict__ A2,
    const int* __restrict__ gidx, const float* __restrict__ W,
    const float* __restrict__ bias, float* __restrict__ C,
    int K, int Nout,
    const float* __restrict__ Rres, const int* __restrict__ midx,
    const float* __restrict__ lnw, const float* __restrict__ lnb){
  extern __shared__ float sm[];
  unsigned* Asm = (unsigned*)sm;             // [2][64*36]
  unsigned* Wsm = (unsigned*)(sm + 2*64*36); // [2][128*36]
  int tid = threadIdx.x, warp = tid>>5, lane = tid&31, gr = lane>>2, tg = lane&3;
  int wm = warp>>1, wn = warp&1;
  int m0 = blockIdx.y*64, n0 = blockIdx.x*128;
  int c4 = (tid&7)<<2;
  int abase = ((c4>>3)<<3) + ((c4>>2)&1);
  int lrow[4], arow[4], wrow[8];
  #pragma unroll
  for (int it=0; it<4; it++){
    int r = (tid + it*128)>>3;
    lrow[it] = m0 + r;
    arow[it] = GATHER ? gidx[m0+r] : (m0+r);
  }
  #pragma unroll
  for (int it=0; it<8; it++) wrow[it] = n0 + ((tid + it*128)>>3);

  float4 va[4], vw[8];
  #pragma unroll
  for (int it=0; it<4; it++){
    va[it] = *(const float4*)(A + (size_t)arow[it]*K + c4);
    if (HASA2){
      float4 u = *(const float4*)(A2 + (size_t)lrow[it]*K + c4);
      va[it].x+=u.x; va[it].y+=u.y; va[it].z+=u.z; va[it].w+=u.w;
    }
  }
  #pragma unroll
  for (int it=0; it<8; it++) vw[it] = *(const float4*)(W + (size_t)wrow[it]*K + c4);
  #pragma unroll
  for (int it=0; it<4; it++){
    unsigned* d = Asm + ((tid+it*128)>>3)*36 + abase;
    d[0]=f2tf(va[it].x); d[2]=f2tf(va[it].y); d[4]=f2tf(va[it].z); d[6]=f2tf(va[it].w);
  }
  #pragma unroll
  for (int it=0; it<8; it++){
    unsigned* d = Wsm + ((tid+it*128)>>3)*36 + abase;
    d[0]=f2tf(vw[it].x); d[2]=f2tf(vw[it].y); d[4]=f2tf(vw[it].z); d[6]=f2tf(vw[it].w);
  }

  float acc[2][8][4];
  #pragma unroll
  for (int mt=0;mt<2;mt++)
    #pragma unroll
    for (int nt=0;nt<8;nt++){acc[mt][nt][0]=acc[mt][nt][1]=acc[mt][nt][2]=acc[mt][nt][3]=0.f;}

  int nc = K >> 5;
  for (int c = 0; c < nc; c++){
    __syncthreads();
    if (c+1 < nc){
      int k0 = (c+1)<<5;
      #pragma unroll
      for (int it=0; it<4; it++){
        va[it] = *(const float4*)(A + (size_t)arow[it]*K + k0 + c4);
        if (HASA2){
          float4 u = *(const float4*)(A2 + (size_t)lrow[it]*K + k0 + c4);
          va[it].x+=u.x; va[it].y+=u.y; va[it].z+=u.z; va[it].w+=u.w;
        }
      }
      #pragma unroll
      for (int it=0; it<8; it++) vw[it] = *(const float4*)(W + (size_t)wrow[it]*K + k0 + c4);
    }
    const unsigned* Ab = Asm + (c&1)*64*36;
    const unsigned* Wb = Wsm + (c&1)*128*36;
    #pragma unroll
    for (int ks=0; ks<4; ks++){
      uint2 alo0 = *(const uint2*)(Ab + (wm*32+   gr)*36 + ks*8 + tg*2);
      uint2 ahi0 = *(const uint2*)(Ab + (wm*32+ 8+gr)*36 + ks*8 + tg*2);
      uint2 alo1 = *(const uint2*)(Ab + (wm*32+16+gr)*36 + ks*8 + tg*2);
      uint2 ahi1 = *(const uint2*)(Ab + (wm*32+24+gr)*36 + ks*8 + tg*2);
      #pragma unroll
      for (int nt=0;nt<8;nt++){
        uint2 bb = *(const uint2*)(Wb + (wn*64+nt*8+gr)*36 + ks*8 + tg*2);
        mma8(acc[0][nt], alo0.x, ahi0.x, alo0.y, ahi0.y, bb.x, bb.y);
        mma8(acc[1][nt], alo1.x, ahi1.x, alo1.y, ahi1.y, bb.x, bb.y);
      }
    }
    if (c+1 < nc){
      unsigned* Ad = Asm + ((c+1)&1)*64*36;
      unsigned* Wd = Wsm + ((c+1)&1)*128*36;
      #pragma unroll
      for (int it=0; it<4; it++){
        unsigned* d = Ad + ((tid+it*128)>>3)*36 + abase;
        d[0]=f2tf(va[it].x); d[2]=f2tf(va[it].y); d[4]=f2tf(va[it].z); d[6]=f2tf(va[it].w);
      }
      #pragma unroll
      for (int it=0; it<8; it++){
        unsigned* d = Wd + ((tid+it*128)>>3)*36 + abase;
        d[0]=f2tf(vw[it].x); d[2]=f2tf(vw[it].y); d[4]=f2tf(vw[it].z); d[6]=f2tf(vw[it].w);
      }
    }
  }

  if (LNM == 0){
    #pragma unroll
    for (int mt=0;mt<2;mt++){
      #pragma unroll
      for (int nt=0;nt<8;nt++){
        int row = m0 + wm*32 + mt*16 + gr;
        int col = n0 + wn*64 + nt*8 + 2*tg;
        float2 bv = *(const float2*)(bias + col);
        float v00 = actf<ACT>(acc[mt][nt][0] + bv.x);
        float v01 = actf<ACT>(acc[mt][nt][1] + bv.y);
        float v10 = actf<ACT>(acc[mt][nt][2] + bv.x);
        float v11 = actf<ACT>(acc[mt][nt][3] + bv.y);
        *(float2*)(C + (size_t)row*Nout + col)     = make_float2(v00, v01);
        *(float2*)(C + (size_t)(row+8)*Nout + col) = make_float2(v10, v11);
      }
    }
  } else {
    // fused LayerNorm epilogue over full 128-col rows
    __syncthreads();
    float2* red = (float2*)sm;   // [64][2]
    int orows[2][2];
    #pragma unroll
    for (int mt=0;mt<2;mt++){
      #pragma unroll
      for (int half=0; half<2; half++){
        int rl_ = wm*32 + mt*16 + half*8 + gr;
        int row = m0 + rl_;
        int orow = (LNM==2) ? midx[row] : row;
        orows[mt][half] = orow;
        const float* R = Rres + (size_t)orow*128;
        float s = 0.f, q = 0.f;
        #pragma unroll
        for (int nt=0;nt<8;nt++){
          int col = wn*64 + nt*8 + 2*tg;
          float2 bv = *(const float2*)(bias + col);
          float2 rv = *(const float2*)(R + col);
          float v0 = acc[mt][nt][half*2+0] + bv.x + rv.x;
          float v1 = acc[mt][nt][half*2+1] + bv.y + rv.y;
          acc[mt][nt][half*2+0] = v0; acc[mt][nt][half*2+1] = v1;
          s += v0 + v1; q += v0*v0 + v1*v1;
        }
        s += __shfl_xor_sync(0xffffffffu, s, 1); q += __shfl_xor_sync(0xffffffffu, q, 1);
        s += __shfl_xor_sync(0xffffffffu, s, 2); q += __shfl_xor_sync(0xffffffffu, q, 2);
        if (tg == 0) red[rl_*2 + wn] = make_float2(s, q);
      }
    }
    __syncthreads();
    #pragma unroll
    for (int mt=0;mt<2;mt++){
      #pragma unroll
      for (int half=0; half<2; half++){
        int rl_ = wm*32 + mt*16 + half*8 + gr;
        float2 p0 = red[rl_*2], p1 = red[rl_*2+1];
        float S = p0.x + p1.x, Q = p0.y + p1.y;
        float mu = S*(1.f/128.f);
        float var = Q*(1.f/128.f) - mu*mu;
        float rs = rsqrtf(var + 1e-5f);
        float* Co = C + (size_t)orows[mt][half]*128;
        #pragma unroll
        for (int nt=0;nt<8;nt++){
          int col = wn*64 + nt*8 + 2*tg;
          float2 wv = *(const float2*)(lnw + col);
          float2 bv = *(const float2*)(lnb + col);
          float o0 = (acc[mt][nt][half*2+0]-mu)*rs*wv.x + bv.x;
          float o1 = (acc[mt][nt][half*2+1]-mu)*rs*wv.y + bv.y;
          *(float2*)(Co + col) = make_float2(o0, o1);
        }
      }
    }
  }
}

// ---------------- flash attention v2 ------------------------------------------
// K-tile 64, double-buffered K/V, 2 CTAs/SM. No mask (every graph = 1024 nodes).
#define ATTN_SMEM ((128*20 + 2*64*20 + 2*64*24 + 128*68)*4)
__global__ void __launch_bounds__(256,2) attn_kernel(const float* __restrict__ qkv,
                                                     float* __restrict__ outp){
  extern __shared__ float sm[];
  float* Qs = sm;                 // [128][20]     pairwise k layout
  float* Ks = sm + 2560;          // [2][64][20]   pairwise k layout
  float* Vs = sm + 5120;          // [2][64][24]   plain layout
  float* Ps = sm + 8192;          // [128][68]     pairwise k layout
  const unsigned* Qu = (const unsigned*)Qs;
  unsigned*       Pu = (unsigned*)Ps;
  int tid = threadIdx.x, warp = tid>>5, lane = tid&31, gr = lane>>2, tg = lane&3;
  int qt = blockIdx.x, bh = blockIdx.y;
  int b = bh>>3, hh = bh&7;
  int qrow0 = b*SEQ_ + qt*128;
  for (int i = tid; i < 512; i += 256){
    int r = i>>2, c4 = (i&3)<<2;
    float4 v = *(const float4*)(qkv + (size_t)(qrow0+r)*384 + hh*16 + c4);
    v.x*=0.25f; v.y*=0.25f; v.z*=0.25f; v.w*=0.25f;   // 1/sqrt(hd)
    st4tf_pair((unsigned*)Qs + r*20, c4, v);
  }
  int rr = tid>>2, cc4 = (tid&3)<<2;   // per-thread K/V load coords (64 rows x 4 f4)
  // prologue: KV tile 0 into buffer 0
  {
    int kr = b*SEQ_ + rr;
    float4 kk = *(const float4*)(qkv + (size_t)kr*384 + 128 + hh*16 + cc4);
    st4tf_pair((unsigned*)Ks + rr*20, cc4, kk);
    float4 vv = *(const float4*)(qkv + (size_t)kr*384 + 256 + hh*16 + cc4);
    st4tf(Vs + rr*24 + cc4, vv);
  }
  int m0 = warp*16;
  int p0 = ((2*tg)&3)*2 + (tg>>1);
  int p1 = ((2*tg+1)&3)*2 + (tg>>1);
  float mrow0 = -1e30f, mrow1 = -1e30f, lrow0 = 0.f, lrow1 = 0.f;
  float o[2][4];
  #pragma unroll
  for (int nt=0;nt<2;nt++){o[nt][0]=o[nt][1]=o[nt][2]=o[nt][3]=0.f;}

  for (int kt = 0; kt < 16; kt++){
    __syncthreads();
    float4 kk, vv;
    if (kt+1 < 16){
      int kr = b*SEQ_ + (kt+1)*64 + rr;
      kk = *(const float4*)(qkv + (size_t)kr*384 + 128 + hh*16 + cc4);
      vv = *(const float4*)(qkv + (size_t)kr*384 + 256 + hh*16 + cc4);
    }
    const unsigned* Kb = (const unsigned*)Ks + (kt&1)*1280;
    const unsigned* Vb = (const unsigned*)Vs + (kt&1)*1536;
    float s[8][4];
    #pragma unroll
    for (int j=0;j<8;j++){s[j][0]=s[j][1]=s[j][2]=s[j][3]=0.f;}
    #pragma unroll
    for (int ks=0; ks<2; ks++){
      uint2 alo = *(const uint2*)(Qu + (m0+gr  )*20 + ks*8 + tg*2);
      uint2 ahi = *(const uint2*)(Qu + (m0+gr+8)*20 + ks*8 + tg*2);
      #pragma unroll
      for (int j=0;j<8;j++){
        uint2 bb = *(const uint2*)(Kb + (j*8+gr)*20 + ks*8 + tg*2);
        mma8(s[j], alo.x, ahi.x, alo.y, ahi.y, bb.x, bb.y);
      }
    }
    // online softmax: rows gr (comps 0,1) and gr+8 (comps 2,3)
    float mx0 = -1e30f, mx1 = -1e30f;
    #pragma unroll
    for (int j=0;j<8;j++){
      mx0 = fmaxf(mx0, fmaxf(s[j][0], s[j][1]));
      mx1 = fmaxf(mx1, fmaxf(s[j][2], s[j][3]));
    }
    mx0 = fmaxf(mx0, __shfl_xor_sync(0xffffffffu, mx0, 1));
    mx0 = fmaxf(mx0, __shfl_xor_sync(0xffffffffu, mx0, 2));
    mx1 = fmaxf(mx1, __shfl_xor_sync(0xffffffffu, mx1, 1));
    mx1 = fmaxf(mx1, __shfl_xor_sync(0xffffffffu, mx1, 2));
    float mn0 = fmaxf(mrow0, mx0), mn1 = fmaxf(mrow1, mx1);
    float al0 = __expf(mrow0 - mn0), al1 = __expf(mrow1 - mn1);
    mrow0 = mn0; mrow1 = mn1;
    float ls0 = 0.f, ls1 = 0.f;
    #pragma unroll
    for (int j=0;j<8;j++){
      s[j][0] = __expf(s[j][0]-mn0); s[j][1] = __expf(s[j][1]-mn0);
      s[j][2] = __expf(s[j][2]-mn1); s[j][3] = __expf(s[j][3]-mn1);
      ls0 += s[j][0]+s[j][1]; ls1 += s[j][2]+s[j][3];
    }
    ls0 += __shfl_xor_sync(0xffffffffu, ls0, 1); ls0 += __shfl_xor_sync(0xffffffffu, ls0, 2);
    ls1 += __shfl_xor_sync(0xffffffffu, ls1, 1); ls1 += __shfl_xor_sync(0xffffffffu, ls1, 2);
    lrow0 = lrow0*al0 + ls0; lrow1 = lrow1*al1 + ls1;
    #pragma unroll
    for (int nt=0;nt<2;nt++){ o[nt][0]*=al0; o[nt][1]*=al0; o[nt][2]*=al1; o[nt][3]*=al1; }
    #pragma unroll
    for (int j=0;j<8;j++){
      Pu[(m0+gr  )*68 + j*8 + p0] = f2tf(s[j][0]);
      Pu[(m0+gr  )*68 + j*8 + p1] = f2tf(s[j][1]);
      Pu[(m0+gr+8)*68 + j*8 + p0] = f2tf(s[j][2]);
      Pu[(m0+gr+8)*68 + j*8 + p1] = f2tf(s[j][3]);
    }
    __syncwarp();
    #pragma unroll
    for (int ks=0; ks<8; ks++){
      uint2 alo = *(const uint2*)(Pu + (m0+gr  )*68 + ks*8 + tg*2);
      uint2 ahi = *(const uint2*)(Pu + (m0+gr+8)*68 + ks*8 + tg*2);
      #pragma unroll
      for (int nt=0; nt<2; nt++){
        unsigned b0 = Vb[(ks*8+tg  )*24 + nt*8 + gr];
        unsigned b1 = Vb[(ks*8+tg+4)*24 + nt*8 + gr];
        mma8(o[nt], alo.x, ahi.x, alo.y, ahi.y, b0, b1);
      }
    }
    if (kt+1 < 16){
      st4tf_pair((unsigned*)Ks + ((kt+1)&1)*1280 + rr*20, cc4, kk);
      st4tf(Vs + ((kt+1)&1)*1536 + rr*24 + cc4, vv);
    }
  }
  float inv0 = 1.f/lrow0, inv1 = 1.f/lrow1;
  #pragma unroll
  for (int nt=0; nt<2; nt++){
    int col = hh*16 + nt*8 + 2*tg;
    size_t r0 = (size_t)(qrow0 + m0 + gr    )*128 + col;
    size_t r1 = (size_t)(qrow0 + m0 + gr + 8)*128 + col;
    *(float2*)(outp + r0) = make_float2(o[nt][0]*inv0, o[nt][1]*inv0);
    *(float2*)(outp + r1) = make_float2(o[nt][2]*inv1, o[nt][3]*inv1);
  }
}

// ---------------- launch ------------------------------------------------------
extern "C" void kernel_launch(void* const* d_in, const int* in_sizes, int n_in,
                              void* d_out, int out_size){
  const float* h         = (const float*)d_in[0];
  const float* edge_attr = (const float*)d_in[1];
  const float* edge_w    = (const float*)d_in[2];
  const float* edge_b    = (const float*)d_in[3];
  const float* gin_w1    = (const float*)d_in[4];
  const float* gin_b1    = (const float*)d_in[5];
  const float* gin_w2    = (const float*)d_in[6];
  const float* gin_b2    = (const float*)d_in[7];
  const float* in_proj_w = (const float*)d_in[8];
  const float* in_proj_b = (const float*)d_in[9];
  const float* out_w     = (const float*)d_in[10];
  const float* out_b     = (const float*)d_in[11];
  const float* ffn_w1    = (const float*)d_in[12];
  const float* ffn_b1    = (const float*)d_in[13];
  const float* ffn_w2    = (const float*)d_in[14];
  const float* ffn_b2    = (const float*)d_in[15];
  const float* ln1_w     = (const float*)d_in[16];
  const float* ln1_b     = (const float*)d_in[17];
  const float* ln2_w     = (const float*)d_in[18];
  const float* ln2_b     = (const float*)d_in[19];
  const float* ln3_w     = (const float*)d_in[20];
  const float* ln3_b     = (const float*)d_in[21];
  const int*   edge_index= (const int*)d_in[22];
  const int*   sort_idx  = (const int*)d_in[24];
  float* outp = (float*)d_out;

  float *agg,*t1,*h1b,*qkvb,*attnb,*h2b,*ffnb;
  cudaGetSymbolAddress((void**)&agg,  g_agg);
  cudaGetSymbolAddress((void**)&t1,   g_t1);
  cudaGetSymbolAddress((void**)&h1b,  g_h1);
  cudaGetSymbolAddress((void**)&qkvb, g_qkv);
  cudaGetSymbolAddress((void**)&attnb,g_attn);
  cudaGetSymbolAddress((void**)&h2b,  g_h2);
  cudaGetSymbolAddress((void**)&ffnb, g_ffn);

  cudaFuncSetAttribute(edge_kernel, cudaFuncAttributeMaxDynamicSharedMemorySize, EDGE_SMEM);
  cudaFuncSetAttribute(gemm_kernel<1,true ,false,0>, cudaFuncAttributeMaxDynamicSharedMemorySize, GEMM_SMEM);
  cudaFuncSetAttribute(gemm_kernel<0,false,false,1>, cudaFuncAttributeMaxDynamicSharedMemorySize, GEMM_SMEM);
  cudaFuncSetAttribute(gemm_kernel<0,false,true ,0>, cudaFuncAttributeMaxDynamicSharedMemorySize, GEMM_SMEM);
  cudaFuncSetAttribute(gemm_kernel<0,false,false,2>, cudaFuncAttributeMaxDynamicSharedMemorySize, GEMM_SMEM);
  cudaFuncSetAttribute(gemm_kernel<2,false,false,0>, cudaFuncAttributeMaxDynamicSharedMemorySize, GEMM_SMEM);
  cudaFuncSetAttribute(attn_kernel, cudaFuncAttributeMaxDynamicSharedMemorySize, ATTN_SMEM);

  // ---- fork: global branch (qkv -> attention) on side stream s2 ----
  cudaEventRecord(g_sh.evFork, 0);
  cudaStreamWaitEvent(g_sh.s2, g_sh.evFork, 0);
  gemm_kernel<0,false,true ,0><<<dim3(3,N_/64),128,GEMM_SMEM,g_sh.s2>>>(
      h, nullptr, sort_idx, in_proj_w, in_proj_b, qkvb, 128, 384,
      nullptr, nullptr, nullptr, nullptr);
  attn_kernel<<<dim3(8,128),256,ATTN_SMEM,g_sh.s2>>>(qkvb, attnb);
  cudaEventRecord(g_sh.evJoin, g_sh.s2);

  // ---- local branch (zero -> edge -> gin MLP + LN1) on main stream ----
  zero_kernel<<<(N_*D_/4 + 255)/256, 256>>>((float4*)agg, N_*D_/4);
  edge_kernel<<<E_/(EDGE_T*128), 256, EDGE_SMEM>>>(edge_attr, edge_w, edge_b, h,
                                                   edge_index, edge_index + E_, agg);
  gemm_kernel<1,true ,false,0><<<dim3(1,N_/64),128,GEMM_SMEM>>>(h,  agg,    nullptr, gin_w1, gin_b1, t1,  128, 128, nullptr, nullptr, nullptr, nullptr);
  gemm_kernel<0,false,false,1><<<dim3(1,N_/64),128,GEMM_SMEM>>>(t1, nullptr,nullptr, gin_w2, gin_b2, h1b, 128, 128, h, nullptr, ln1_w, ln1_b);

  // ---- join: out projection + LN2 (needs h1b and attnb) ----
  cudaStreamWaitEvent(0, g_sh.evJoin, 0);
  gemm_kernel<0,false,false,2><<<dim3(1,N_/64),128,GEMM_SMEM>>>(attnb, nullptr,nullptr, out_w, out_b, h2b, 128, 128, h1b, sort_idx, ln2_w, ln2_b);
  // ---- FFN: gelu gemm, then ffn2 + fused LN3 -> final output ----
  gemm_kernel<2,false,false,0><<<dim3(4,N_/64),128,GEMM_SMEM>>>(h2b, nullptr,nullptr, ffn_w1, ffn_b1, ffnb, 128, 512, nullptr, nullptr, nullptr, nullptr);
  gemm_kernel<0,false,false,1><<<dim3(1,N_/64),128,GEMM_SMEM>>>(ffnb,nullptr,nullptr, ffn_w2, ffn_b2, outp, 512, 128, h2b, nullptr, ln3_w, ln3_b);
}

// round 16
// speedup vs baseline: 1.1925x; 1.1320x over previous
#include <cuda_runtime.h>
#include <math.h>

#define D_    128
#define N_    16384
#define E_    524288
#define B_    16
#define SEQ_  1024
#define DFF_  512

// ---------------- scratch (device globals: no allocations allowed) ----------
__device__ float g_agg [N_*D_];
__device__ float g_t1  [N_*D_];
__device__ float g_h1  [N_*D_];
__device__ float g_qkv [N_*3*D_];
__device__ float g_attn[N_*D_];
__device__ float g_h2  [N_*D_];
__device__ float g_ffn [N_*DFF_];

// ---------------- streams/events for branch overlap (created once at load) ---
struct StreamHolder {
  cudaStream_t s2; cudaEvent_t evFork, evJoin;
  StreamHolder(){
    cudaStreamCreateWithFlags(&s2, cudaStreamNonBlocking);
    cudaEventCreateWithFlags(&evFork, cudaEventDisableTiming);
    cudaEventCreateWithFlags(&evJoin, cudaEventDisableTiming);
  }
};
static StreamHolder g_sh;

// ---------------- helpers ----------------------------------------------------
__device__ __forceinline__ unsigned f2tf(float f){
  unsigned r; asm("cvt.rna.tf32.f32 %0, %1;" : "=r"(r) : "f"(f)); return r;
}
__device__ __forceinline__ unsigned bf2(float hi, float lo){
  unsigned r; asm("cvt.rn.bf16x2.f32 %0, %1, %2;" : "=r"(r) : "f"(hi), "f"(lo)); return r;
}
__device__ __forceinline__ void st4tf(float* dst, float4 v){
  unsigned* d = (unsigned*)dst;
  d[0]=f2tf(v.x); d[1]=f2tf(v.y); d[2]=f2tf(v.z); d[3]=f2tf(v.w);
}
// scatter a float4 of 4 consecutive k (c4 multiple of 4, 0..28 within a 32-chunk)
// into pairwise layout: within each 8-group, k-local kl at pos (kl&3)*2 + (kl>>2)
__device__ __forceinline__ void st4tf_pair(unsigned* rowbase, int c4, float4 v){
  int base = ((c4>>3)<<3) + ((c4>>2)&1);
  rowbase[base+0]=f2tf(v.x); rowbase[base+2]=f2tf(v.y);
  rowbase[base+4]=f2tf(v.z); rowbase[base+6]=f2tf(v.w);
}
__device__ __forceinline__ void mma8(float c[4], unsigned a0,unsigned a1,unsigned a2,unsigned a3,
                                     unsigned b0, unsigned b1){
  asm volatile("mma.sync.aligned.m16n8k8.row.col.f32.tf32.tf32.f32 "
      "{%0,%1,%2,%3},{%4,%5,%6,%7},{%8,%9},{%0,%1,%2,%3};"
      : "+f"(c[0]),"+f"(c[1]),"+f"(c[2]),"+f"(c[3])
      : "r"(a0),"r"(a1),"r"(a2),"r"(a3),"r"(b0),"r"(b1));
}
template<int ACT> __device__ __forceinline__ float actf(float x){
  if (ACT==1) return fmaxf(x, 0.f);
  if (ACT==2) return 0.5f*x*(1.f + erff(x*0.70710678118654752f));
  return x;
}

// ---------------- zero init --------------------------------------------------
__global__ void zero_kernel(float4* p, int n){
  int i = blockIdx.x*blockDim.x + threadIdx.x;
  if (i < n) p[i] = make_float4(0.f,0.f,0.f,0.f);
}

// ---------------- fused edge stage v3 (bf16-packed operands) ------------------
// 1024 blocks x 256 threads, 2 CTAs/SM, 64KB smem. W resident as bf16 {k,k+4}
// pairs (4 chunk tiles), A double-buffered bf16 {row,row+8} pairs.
// e = ea@W^T + b (tf32 mma, fp32 acc); msg = relu(h[src]+e); atomicAdd(float2).
#define EDGE_T 4
// Wres: [4][128 cols][20] u32 ; Abuf: [2][8 tiles][8 rp][40] u32
#define EDGE_SMEM ((4*128*20 + 2*2560)*4 + 512 + 2048)
__global__ void __launch_bounds__(256,2) edge_kernel(
    const float* __restrict__ ea, const float* __restrict__ Wt,
    const float* __restrict__ eb, const float* __restrict__ h,
    const int* __restrict__ src, const int* __restrict__ dst,
    float* __restrict__ agg){
  extern __shared__ unsigned smu[];
  unsigned* Wres = smu;                     // [4][128][20]
  unsigned* Abuf = smu + 4*128*20;          // [2][2560]
  float*    s_eb = (float*)(smu + 4*128*20 + 2*2560);
  int*      sidx = (int*)(s_eb + 128);      // [2][256]
  int tid = threadIdx.x;

  // ---- W resident: bf16 pairs {lo:k, hi:k+4}, pos (k>>3)*4 + (k&3) ----------
  {
    int colW = tid>>1, sW = tid&1;
    #pragma unroll
    for (int ck=0; ck<4; ck++){
      const float* wr = Wt + (size_t)colW*128 + ck*32 + sW*16;
      float4 f0 = *(const float4*)(wr);
      float4 f1 = *(const float4*)(wr+4);
      float4 f2 = *(const float4*)(wr+8);
      float4 f3 = *(const float4*)(wr+12);
      unsigned* d = Wres + ck*2560 + colW*20 + sW*8;
      *(uint4*)(d)   = make_uint4(bf2(f1.x,f0.x), bf2(f1.y,f0.y), bf2(f1.z,f0.z), bf2(f1.w,f0.w));
      *(uint4*)(d+4) = make_uint4(bf2(f3.x,f2.x), bf2(f3.y,f2.y), bf2(f3.z,f2.z), bf2(f3.w,f2.w));
    }
  }
  if (tid < 128) s_eb[tid] = eb[tid];

  // A loader coords: gA = rp-pair id (tile = gA>>3, rp = gA&7), sA = 8-k slot
  int gA = tid>>2, sA = tid&3;
  int r0l = (gA>>3)*16 + (gA&7);        // local row in [0,128)
  int r1l = r0l + 8;
  unsigned* Adst0 = Abuf + (gA>>3)*320 + (gA&7)*40 + sA*8;

  // prologue: tile0 indices + chunk0 into buf0
  {
    int e0 = blockIdx.x*(EDGE_T*128);
    sidx[tid] = (tid<128) ? src[e0+tid] : dst[e0+tid-128];
    const float* p0 = ea + (size_t)(e0+r0l)*128 + sA*8;
    const float* p1 = ea + (size_t)(e0+r1l)*128 + sA*8;
    float4 a0 = *(const float4*)(p0), a1 = *(const float4*)(p0+4);
    float4 a2 = *(const float4*)(p1), a3 = *(const float4*)(p1+4);
    *(uint4*)(Adst0)   = make_uint4(bf2(a2.x,a0.x), bf2(a3.x,a1.x), bf2(a2.y,a0.y), bf2(a3.y,a1.y));
    *(uint4*)(Adst0+4) = make_uint4(bf2(a2.z,a0.z), bf2(a3.z,a1.z), bf2(a2.w,a0.w), bf2(a3.w,a1.w));
  }

  int warp = tid>>5, lane = tid&31, gr = lane>>2, tg = lane&3;
  int wm = warp>>1, wn = warp&1;   // rows wm*32+, cols wn*64+
  float acc[2][8][4];
  #pragma unroll
  for (int mt=0;mt<2;mt++)
    #pragma unroll
    for (int nt=0;nt<8;nt++){acc[mt][nt][0]=acc[mt][nt][1]=acc[mt][nt][2]=acc[mt][nt][3]=0.f;}
  float4 va[4]; int idxreg = 0;
  const int NIT = EDGE_T*4;
  for (int i = 0; i < NIT; i++){
    __syncthreads();
    int ip = i+1;
    if (ip < NIT){
      int t_ = ip>>2, c_ = ip&3;
      int e0 = blockIdx.x*(EDGE_T*128) + t_*128;
      const float* p0 = ea + (size_t)(e0+r0l)*128 + c_*32 + sA*8;
      const float* p1 = ea + (size_t)(e0+r1l)*128 + c_*32 + sA*8;
      va[0] = *(const float4*)(p0); va[1] = *(const float4*)(p0+4);
      va[2] = *(const float4*)(p1); va[3] = *(const float4*)(p1+4);
      if (c_ == 0) idxreg = (tid<128) ? src[e0+tid] : dst[e0+tid-128];
    }
    const unsigned* Ab = Abuf + (i&1)*2560;
    const unsigned* Wb = Wres + (i&3)*2560;
    #pragma unroll
    for (int ks=0; ks<4; ks++){
      uint2 A0 = *(const uint2*)(Ab + (wm*2+0)*320 + gr*40 + ks*8 + tg*2);
      uint2 A1 = *(const uint2*)(Ab + (wm*2+1)*320 + gr*40 + ks*8 + tg*2);
      unsigned a00 = A0.x<<16, a01 = A0.x&0xFFFF0000u;
      unsigned a02 = A0.y<<16, a03 = A0.y&0xFFFF0000u;
      unsigned a10 = A1.x<<16, a11 = A1.x&0xFFFF0000u;
      unsigned a12 = A1.y<<16, a13 = A1.y&0xFFFF0000u;
      #pragma unroll
      for (int nt=0;nt<8;nt++){
        unsigned bu = Wb[(wn*64+nt*8+gr)*20 + ks*4 + tg];
        unsigned b0 = bu<<16, b1 = bu&0xFFFF0000u;
        mma8(acc[0][nt], a00,a01,a02,a03, b0,b1);
        mma8(acc[1][nt], a10,a11,a12,a13, b0,b1);
      }
    }
    if (ip < NIT){
      unsigned* Ad = Abuf + (ip&1)*2560 + (gA>>3)*320 + (gA&7)*40 + sA*8;
      *(uint4*)(Ad)   = make_uint4(bf2(va[2].x,va[0].x), bf2(va[3].x,va[1].x), bf2(va[2].y,va[0].y), bf2(va[3].y,va[1].y));
      *(uint4*)(Ad+4) = make_uint4(bf2(va[2].z,va[0].z), bf2(va[3].z,va[1].z), bf2(va[2].w,va[0].w), bf2(va[3].w,va[1].w));
      if ((ip&3)==0) sidx[((ip>>2)&1)*256 + tid] = idxreg;
    }
    if ((i&3)==3){
      int tp = ((i>>2)&1)*256;
      #pragma unroll
      for (int mt=0;mt<2;mt++){
        #pragma unroll
        for (int half=0; half<2; half++){
          int r = wm*32 + mt*16 + half*8 + gr;
          int sid = sidx[tp+r], did = sidx[tp+128+r];
          const float* hrow = h   + (size_t)sid*128;
          float*       arow = agg + (size_t)did*128;
          #pragma unroll
          for (int nt=0;nt<8;nt++){
            int col = wn*64 + nt*8 + 2*tg;
            float2 hv = *(const float2*)(hrow + col);
            float v0 = acc[mt][nt][half*2+0] + s_eb[col]   + hv.x;
            float v1 = acc[mt][nt][half*2+1] + s_eb[col+1] + hv.y;
            atomicAdd((float2*)(arow + col), make_float2(fmaxf(v0,0.f), fmaxf(v1,0.f)));
          }
        }
      }
      #pragma unroll
      for (int mt=0;mt<2;mt++)
        #pragma unroll
        for (int nt=0;nt<8;nt++){acc[mt][nt][0]=acc[mt][nt][1]=acc[mt][nt][2]=acc[mt][nt][3]=0.f;}
    }
  }
}

// ---------------- generic tf32 GEMM: C = act(A(+A2)@W^T + bias) --------------
// block: 128 threads, tile 64(M) x 128(N), double-buffered 32-wide k-chunks.
// LNM: 0 = plain store; 1 = C[row] = LN(R[row] + out); 2 = orow=midx[row],
//      C[orow] = LN(R[orow] + out).  (LNM requires Nout==128, grid.x==1.)
#define GEMM_SMEM ((2*64*36 + 2*128*36)*4)
template<int ACT, bool HASA2, bool GATHER, int LNM>
__global__ void __launch_bounds__(128,3) gemm_kernel(
    const float* __restrict__ A, const float* __restrict__ A2,
    const int* __restrict__ gidx, const float* __restrict__ W,
    const float* __restrict__ bias, float* __restrict__ C,
    int K, int Nout,
    const float* __restrict__ Rres, const int* __restrict__ midx,
    const float* __restrict__ lnw, const float* __restrict__ lnb){
  extern __shared__ float sm[];
  unsigned* Asm = (unsigned*)sm;             // [2][64*36]
  unsigned* Wsm = (unsigned*)(sm + 2*64*36); // [2][128*36]
  int tid = threadIdx.x, warp = tid>>5, lane = tid&31, gr = lane>>2, tg = lane&3;
  int wm = warp>>1, wn = warp&1;
  int m0 = blockIdx.y*64, n0 = blockIdx.x*128;
  int c4 = (tid&7)<<2;
  int abase = ((c4>>3)<<3) + ((c4>>2)&1);
  int lrow[4], arow[4], wrow[8];
  #pragma unroll
  for (int it=0; it<4; it++){
    int r = (tid + it*128)>>3;
    lrow[it] = m0 + r;
    arow[it] = GATHER ? gidx[m0+r] : (m0+r);
  }
  #pragma unroll
  for (int it=0; it<8; it++) wrow[it] = n0 + ((tid + it*128)>>3);

  float4 va[4], vw[8];
  #pragma unroll
  for (int it=0; it<4; it++){
    va[it] = *(const float4*)(A + (size_t)arow[it]*K + c4);
    if (HASA2){
      float4 u = *(const float4*)(A2 + (size_t)lrow[it]*K + c4);
      va[it].x+=u.x; va[it].y+=u.y; va[it].z+=u.z; va[it].w+=u.w;
    }
  }
  #pragma unroll
  for (int it=0; it<8; it++) vw[it] = *(const float4*)(W + (size_t)wrow[it]*K + c4);
  #pragma unroll
  for (int it=0; it<4; it++){
    unsigned* d = Asm + ((tid+it*128)>>3)*36 + abase;
    d[0]=f2tf(va[it].x); d[2]=f2tf(va[it].y); d[4]=f2tf(va[it].z); d[6]=f2tf(va[it].w);
  }
  #pragma unroll
  for (int it=0; it<8; it++){
    unsigned* d = Wsm + ((tid+it*128)>>3)*36 + abase;
    d[0]=f2tf(vw[it].x); d[2]=f2tf(vw[it].y); d[4]=f2tf(vw[it].z); d[6]=f2tf(vw[it].w);
  }

  float acc[2][8][4];
  #pragma unroll
  for (int mt=0;mt<2;mt++)
    #pragma unroll
    for (int nt=0;nt<8;nt++){acc[mt][nt][0]=acc[mt][nt][1]=acc[mt][nt][2]=acc[mt][nt][3]=0.f;}

  int nc = K >> 5;
  for (int c = 0; c < nc; c++){
    __syncthreads();
    if (c+1 < nc){
      int k0 = (c+1)<<5;
      #pragma unroll
      for (int it=0; it<4; it++){
        va[it] = *(const float4*)(A + (size_t)arow[it]*K + k0 + c4);
        if (HASA2){
          float4 u = *(const float4*)(A2 + (size_t)lrow[it]*K + k0 + c4);
          va[it].x+=u.x; va[it].y+=u.y; va[it].z+=u.z; va[it].w+=u.w;
        }
      }
      #pragma unroll
      for (int it=0; it<8; it++) vw[it] = *(const float4*)(W + (size_t)wrow[it]*K + k0 + c4);
    }
    const unsigned* Ab = Asm + (c&1)*64*36;
    const unsigned* Wb = Wsm + (c&1)*128*36;
    #pragma unroll
    for (int ks=0; ks<4; ks++){
      uint2 alo0 = *(const uint2*)(Ab + (wm*32+   gr)*36 + ks*8 + tg*2);
      uint2 ahi0 = *(const uint2*)(Ab + (wm*32+ 8+gr)*36 + ks*8 + tg*2);
      uint2 alo1 = *(const uint2*)(Ab + (wm*32+16+gr)*36 + ks*8 + tg*2);
      uint2 ahi1 = *(const uint2*)(Ab + (wm*32+24+gr)*36 + ks*8 + tg*2);
      #pragma unroll
      for (int nt=0;nt<8;nt++){
        uint2 bb = *(const uint2*)(Wb + (wn*64+nt*8+gr)*36 + ks*8 + tg*2);
        mma8(acc[0][nt], alo0.x, ahi0.x, alo0.y, ahi0.y, bb.x, bb.y);
        mma8(acc[1][nt], alo1.x, ahi1.x, alo1.y, ahi1.y, bb.x, bb.y);
      }
    }
    if (c+1 < nc){
      unsigned* Ad = Asm + ((c+1)&1)*64*36;
      unsigned* Wd = Wsm + ((c+1)&1)*128*36;
      #pragma unroll
      for (int it=0; it<4; it++){
        unsigned* d = Ad + ((tid+it*128)>>3)*36 + abase;
        d[0]=f2tf(va[it].x); d[2]=f2tf(va[it].y); d[4]=f2tf(va[it].z); d[6]=f2tf(va[it].w);
      }
      #pragma unroll
      for (int it=0; it<8; it++){
        unsigned* d = Wd + ((tid+it*128)>>3)*36 + abase;
        d[0]=f2tf(vw[it].x); d[2]=f2tf(vw[it].y); d[4]=f2tf(vw[it].z); d[6]=f2tf(vw[it].w);
      }
    }
  }

  if (LNM == 0){
    #pragma unroll
    for (int mt=0;mt<2;mt++){
      #pragma unroll
      for (int nt=0;nt<8;nt++){
        int row = m0 + wm*32 + mt*16 + gr;
        int col = n0 + wn*64 + nt*8 + 2*tg;
        float2 bv = *(const float2*)(bias + col);
        float v00 = actf<ACT>(acc[mt][nt][0] + bv.x);
        float v01 = actf<ACT>(acc[mt][nt][1] + bv.y);
        float v10 = actf<ACT>(acc[mt][nt][2] + bv.x);
        float v11 = actf<ACT>(acc[mt][nt][3] + bv.y);
        *(float2*)(C + (size_t)row*Nout + col)     = make_float2(v00, v01);
        *(float2*)(C + (size_t)(row+8)*Nout + col) = make_float2(v10, v11);
      }
    }
  } else {
    // fused LayerNorm epilogue over full 128-col rows
    __syncthreads();
    float2* red = (float2*)sm;   // [64][2]
    int orows[2][2];
    #pragma unroll
    for (int mt=0;mt<2;mt++){
      #pragma unroll
      for (int half=0; half<2; half++){
        int rl_ = wm*32 + mt*16 + half*8 + gr;
        int row = m0 + rl_;
        int orow = (LNM==2) ? midx[row] : row;
        orows[mt][half] = orow;
        const float* R = Rres + (size_t)orow*128;
        float s = 0.f, q = 0.f;
        #pragma unroll
        for (int nt=0;nt<8;nt++){
          int col = wn*64 + nt*8 + 2*tg;
          float2 bv = *(const float2*)(bias + col);
          float2 rv = *(const float2*)(R + col);
          float v0 = acc[mt][nt][half*2+0] + bv.x + rv.x;
          float v1 = acc[mt][nt][half*2+1] + bv.y + rv.y;
          acc[mt][nt][half*2+0] = v0; acc[mt][nt][half*2+1] = v1;
          s += v0 + v1; q += v0*v0 + v1*v1;
        }
        s += __shfl_xor_sync(0xffffffffu, s, 1); q += __shfl_xor_sync(0xffffffffu, q, 1);
        s += __shfl_xor_sync(0xffffffffu, s, 2); q += __shfl_xor_sync(0xffffffffu, q, 2);
        if (tg == 0) red[rl_*2 + wn] = make_float2(s, q);
      }
    }
    __syncthreads();
    #pragma unroll
    for (int mt=0;mt<2;mt++){
      #pragma unroll
      for (int half=0; half<2; half++){
        int rl_ = wm*32 + mt*16 + half*8 + gr;
        float2 p0 = red[rl_*2], p1 = red[rl_*2+1];
        float S = p0.x + p1.x, Q = p0.y + p1.y;
        float mu = S*(1.f/128.f);
        float var = Q*(1.f/128.f) - mu*mu;
        float rs = rsqrtf(var + 1e-5f);
        float* Co = C + (size_t)orows[mt][half]*128;
        #pragma unroll
        for (int nt=0;nt<8;nt++){
          int col = wn*64 + nt*8 + 2*tg;
          float2 wv = *(const float2*)(lnw + col);
          float2 bv = *(const float2*)(lnb + col);
          float o0 = (acc[mt][nt][half*2+0]-mu)*rs*wv.x + bv.x;
          float o1 = (acc[mt][nt][half*2+1]-mu)*rs*wv.y + bv.y;
          *(float2*)(Co + col) = make_float2(o0, o1);
        }
      }
    }
  }
}

// ---------------- flash attention v2 ------------------------------------------
// K-tile 64, double-buffered K/V, 2 CTAs/SM. No mask (every graph = 1024 nodes).
#define ATTN_SMEM ((128*20 + 2*64*20 + 2*64*24 + 128*68)*4)
__global__ void __launch_bounds__(256,2) attn_kernel(const float* __restrict__ qkv,
                                                     float* __restrict__ outp){
  extern __shared__ float sm[];
  float* Qs = sm;                 // [128][20]     pairwise k layout
  float* Ks = sm + 2560;          // [2][64][20]   pairwise k layout
  float* Vs = sm + 5120;          // [2][64][24]   plain layout
  float* Ps = sm + 8192;          // [128][68]     pairwise k layout
  const unsigned* Qu = (const unsigned*)Qs;
  unsigned*       Pu = (unsigned*)Ps;
  int tid = threadIdx.x, warp = tid>>5, lane = tid&31, gr = lane>>2, tg = lane&3;
  int qt = blockIdx.x, bh = blockIdx.y;
  int b = bh>>3, hh = bh&7;
  int qrow0 = b*SEQ_ + qt*128;
  for (int i = tid; i < 512; i += 256){
    int r = i>>2, c4 = (i&3)<<2;
    float4 v = *(const float4*)(qkv + (size_t)(qrow0+r)*384 + hh*16 + c4);
    v.x*=0.25f; v.y*=0.25f; v.z*=0.25f; v.w*=0.25f;   // 1/sqrt(hd)
    st4tf_pair((unsigned*)Qs + r*20, c4, v);
  }
  int rr = tid>>2, cc4 = (tid&3)<<2;   // per-thread K/V load coords (64 rows x 4 f4)
  // prologue: KV tile 0 into buffer 0
  {
    int kr = b*SEQ_ + rr;
    float4 kk = *(const float4*)(qkv + (size_t)kr*384 + 128 + hh*16 + cc4);
    st4tf_pair((unsigned*)Ks + rr*20, cc4, kk);
    float4 vv = *(const float4*)(qkv + (size_t)kr*384 + 256 + hh*16 + cc4);
    st4tf(Vs + rr*24 + cc4, vv);
  }
  int m0 = warp*16;
  int p0 = ((2*tg)&3)*2 + (tg>>1);
  int p1 = ((2*tg+1)&3)*2 + (tg>>1);
  float mrow0 = -1e30f, mrow1 = -1e30f, lrow0 = 0.f, lrow1 = 0.f;
  float o[2][4];
  #pragma unroll
  for (int nt=0;nt<2;nt++){o[nt][0]=o[nt][1]=o[nt][2]=o[nt][3]=0.f;}

  for (int kt = 0; kt < 16; kt++){
    __syncthreads();
    float4 kk, vv;
    if (kt+1 < 16){
      int kr = b*SEQ_ + (kt+1)*64 + rr;
      kk = *(const float4*)(qkv + (size_t)kr*384 + 128 + hh*16 + cc4);
      vv = *(const float4*)(qkv + (size_t)kr*384 + 256 + hh*16 + cc4);
    }
    const unsigned* Kb = (const unsigned*)Ks + (kt&1)*1280;
    const unsigned* Vb = (const unsigned*)Vs + (kt&1)*1536;
    float s[8][4];
    #pragma unroll
    for (int j=0;j<8;j++){s[j][0]=s[j][1]=s[j][2]=s[j][3]=0.f;}
    #pragma unroll
    for (int ks=0; ks<2; ks++){
      uint2 alo = *(const uint2*)(Qu + (m0+gr  )*20 + ks*8 + tg*2);
      uint2 ahi = *(const uint2*)(Qu + (m0+gr+8)*20 + ks*8 + tg*2);
      #pragma unroll
      for (int j=0;j<8;j++){
        uint2 bb = *(const uint2*)(Kb + (j*8+gr)*20 + ks*8 + tg*2);
        mma8(s[j], alo.x, ahi.x, alo.y, ahi.y, bb.x, bb.y);
      }
    }
    // online softmax: rows gr (comps 0,1) and gr+8 (comps 2,3)
    float mx0 = -1e30f, mx1 = -1e30f;
    #pragma unroll
    for (int j=0;j<8;j++){
      mx0 = fmaxf(mx0, fmaxf(s[j][0], s[j][1]));
      mx1 = fmaxf(mx1, fmaxf(s[j][2], s[j][3]));
    }
    mx0 = fmaxf(mx0, __shfl_xor_sync(0xffffffffu, mx0, 1));
    mx0 = fmaxf(mx0, __shfl_xor_sync(0xffffffffu, mx0, 2));
    mx1 = fmaxf(mx1, __shfl_xor_sync(0xffffffffu, mx1, 1));
    mx1 = fmaxf(mx1, __shfl_xor_sync(0xffffffffu, mx1, 2));
    float mn0 = fmaxf(mrow0, mx0), mn1 = fmaxf(mrow1, mx1);
    float al0 = __expf(mrow0 - mn0), al1 = __expf(mrow1 - mn1);
    mrow0 = mn0; mrow1 = mn1;
    float ls0 = 0.f, ls1 = 0.f;
    #pragma unroll
    for (int j=0;j<8;j++){
      s[j][0] = __expf(s[j][0]-mn0); s[j][1] = __expf(s[j][1]-mn0);
      s[j][2] = __expf(s[j][2]-mn1); s[j][3] = __expf(s[j][3]-mn1);
      ls0 += s[j][0]+s[j][1]; ls1 += s[j][2]+s[j][3];
    }
    ls0 += __shfl_xor_sync(0xffffffffu, ls0, 1); ls0 += __shfl_xor_sync(0xffffffffu, ls0, 2);
    ls1 += __shfl_xor_sync(0xffffffffu, ls1, 1); ls1 += __shfl_xor_sync(0xffffffffu, ls1, 2);
    lrow0 = lrow0*al0 + ls0; lrow1 = lrow1*al1 + ls1;
    #pragma unroll
    for (int nt=0;nt<2;nt++){ o[nt][0]*=al0; o[nt][1]*=al0; o[nt][2]*=al1; o[nt][3]*=al1; }
    #pragma unroll
    for (int j=0;j<8;j++){
      Pu[(m0+gr  )*68 + j*8 + p0] = f2tf(s[j][0]);
      Pu[(m0+gr  )*68 + j*8 + p1] = f2tf(s[j][1]);
      Pu[(m0+gr+8)*68 + j*8 + p0] = f2tf(s[j][2]);
      Pu[(m0+gr+8)*68 + j*8 + p1] = f2tf(s[j][3]);
    }
    __syncwarp();
    #pragma unroll
    for (int ks=0; ks<8; ks++){
      uint2 alo = *(const uint2*)(Pu + (m0+gr  )*68 + ks*8 + tg*2);
      uint2 ahi = *(const uint2*)(Pu + (m0+gr+8)*68 + ks*8 + tg*2);
      #pragma unroll
      for (int nt=0; nt<2; nt++){
        unsigned b0 = Vb[(ks*8+tg  )*24 + nt*8 + gr];
        unsigned b1 = Vb[(ks*8+tg+4)*24 + nt*8 + gr];
        mma8(o[nt], alo.x, ahi.x, alo.y, ahi.y, b0, b1);
      }
    }
    if (kt+1 < 16){
      st4tf_pair((unsigned*)Ks + ((kt+1)&1)*1280 + rr*20, cc4, kk);
      st4tf(Vs + ((kt+1)&1)*1536 + rr*24 + cc4, vv);
    }
  }
  float inv0 = 1.f/lrow0, inv1 = 1.f/lrow1;
  #pragma unroll
  for (int nt=0; nt<2; nt++){
    int col = hh*16 + nt*8 + 2*tg;
    size_t r0 = (size_t)(qrow0 + m0 + gr    )*128 + col;
    size_t r1 = (size_t)(qrow0 + m0 + gr + 8)*128 + col;
    *(float2*)(outp + r0) = make_float2(o[nt][0]*inv0, o[nt][1]*inv0);
    *(float2*)(outp + r1) = make_float2(o[nt][2]*inv1, o[nt][3]*inv1);
  }
}

// ---------------- launch ------------------------------------------------------
extern "C" void kernel_launch(void* const* d_in, const int* in_sizes, int n_in,
                              void* d_out, int out_size){
  const float* h         = (const float*)d_in[0];
  const float* edge_attr = (const float*)d_in[1];
  const float* edge_w    = (const float*)d_in[2];
  const float* edge_b    = (const float*)d_in[3];
  const float* gin_w1    = (const float*)d_in[4];
  const float* gin_b1    = (const float*)d_in[5];
  const float* gin_w2    = (const float*)d_in[6];
  const float* gin_b2    = (const float*)d_in[7];
  const float* in_proj_w = (const float*)d_in[8];
  const float* in_proj_b = (const float*)d_in[9];
  const float* out_w     = (const float*)d_in[10];
  const float* out_b     = (const float*)d_in[11];
  const float* ffn_w1    = (const float*)d_in[12];
  const float* ffn_b1    = (const float*)d_in[13];
  const float* ffn_w2    = (const float*)d_in[14];
  const float* ffn_b2    = (const float*)d_in[15];
  const float* ln1_w     = (const float*)d_in[16];
  const float* ln1_b     = (const float*)d_in[17];
  const float* ln2_w     = (const float*)d_in[18];
  const float* ln2_b     = (const float*)d_in[19];
  const float* ln3_w     = (const float*)d_in[20];
  const float* ln3_b     = (const float*)d_in[21];
  const int*   edge_index= (const int*)d_in[22];
  const int*   sort_idx  = (const int*)d_in[24];
  float* outp = (float*)d_out;

  float *agg,*t1,*h1b,*qkvb,*attnb,*h2b,*ffnb;
  cudaGetSymbolAddress((void**)&agg,  g_agg);
  cudaGetSymbolAddress((void**)&t1,   g_t1);
  cudaGetSymbolAddress((void**)&h1b,  g_h1);
  cudaGetSymbolAddress((void**)&qkvb, g_qkv);
  cudaGetSymbolAddress((void**)&attnb,g_attn);
  cudaGetSymbolAddress((void**)&h2b,  g_h2);
  cudaGetSymbolAddress((void**)&ffnb, g_ffn);

  cudaFuncSetAttribute(edge_kernel, cudaFuncAttributeMaxDynamicSharedMemorySize, EDGE_SMEM);
  cudaFuncSetAttribute(gemm_kernel<1,true ,false,0>, cudaFuncAttributeMaxDynamicSharedMemorySize, GEMM_SMEM);
  cudaFuncSetAttribute(gemm_kernel<0,false,false,1>, cudaFuncAttributeMaxDynamicSharedMemorySize, GEMM_SMEM);
  cudaFuncSetAttribute(gemm_kernel<0,false,true ,0>, cudaFuncAttributeMaxDynamicSharedMemorySize, GEMM_SMEM);
  cudaFuncSetAttribute(gemm_kernel<0,false,false,2>, cudaFuncAttributeMaxDynamicSharedMemorySize, GEMM_SMEM);
  cudaFuncSetAttribute(gemm_kernel<2,false,false,0>, cudaFuncAttributeMaxDynamicSharedMemorySize, GEMM_SMEM);
  cudaFuncSetAttribute(attn_kernel, cudaFuncAttributeMaxDynamicSharedMemorySize, ATTN_SMEM);

  // ---- fork: global branch (qkv -> attention) on side stream s2 ----
  cudaEventRecord(g_sh.evFork, 0);
  cudaStreamWaitEvent(g_sh.s2, g_sh.evFork, 0);
  gemm_kernel<0,false,true ,0><<<dim3(3,N_/64),128,GEMM_SMEM,g_sh.s2>>>(
      h, nullptr, sort_idx, in_proj_w, in_proj_b, qkvb, 128, 384,
      nullptr, nullptr, nullptr, nullptr);
  attn_kernel<<<dim3(8,128),256,ATTN_SMEM,g_sh.s2>>>(qkvb, attnb);
  cudaEventRecord(g_sh.evJoin, g_sh.s2);

  // ---- local branch (zero -> edge -> gin MLP + LN1) on main stream ----
  zero_kernel<<<(N_*D_/4 + 255)/256, 256>>>((float4*)agg, N_*D_/4);
  edge_kernel<<<E_/(EDGE_T*128), 256, EDGE_SMEM>>>(edge_attr, edge_w, edge_b, h,
                                                   edge_index, edge_index + E_, agg);
  gemm_kernel<1,true ,false,0><<<dim3(1,N_/64),128,GEMM_SMEM>>>(h,  agg,    nullptr, gin_w1, gin_b1, t1,  128, 128, nullptr, nullptr, nullptr, nullptr);
  gemm_kernel<0,false,false,1><<<dim3(1,N_/64),128,GEMM_SMEM>>>(t1, nullptr,nullptr, gin_w2, gin_b2, h1b, 128, 128, h, nullptr, ln1_w, ln1_b);

  // ---- join: out projection + LN2 (needs h1b and attnb) ----
  cudaStreamWaitEvent(0, g_sh.evJoin, 0);
  gemm_kernel<0,false,false,2><<<dim3(1,N_/64),128,GEMM_SMEM>>>(attnb, nullptr,nullptr, out_w, out_b, h2b, 128, 128, h1b, sort_idx, ln2_w, ln2_b);
  // ---- FFN: gelu gemm, then ffn2 + fused LN3 -> final output ----
  gemm_kernel<2,false,false,0><<<dim3(4,N_/64),128,GEMM_SMEM>>>(h2b, nullptr,nullptr, ffn_w1, ffn_b1, ffnb, 128, 512, nullptr, nullptr, nullptr, nullptr);
  gemm_kernel<0,false,false,1><<<dim3(1,N_/64),128,GEMM_SMEM>>>(ffnb,nullptr,nullptr, ffn_w2, ffn_b2, outp, 512, 128, h2b, nullptr, ln3_w, ln3_b);
}

// round 17
// speedup vs baseline: 1.3469x; 1.1295x over previous
#include <cuda_runtime.h>
#include <math.h>

#define D_    128
#define N_    16384
#define E_    524288
#define B_    16
#define SEQ_  1024
#define DFF_  512

// ---------------- scratch (device globals: no allocations allowed) ----------
__device__ float g_agg [N_*D_];
__device__ float g_t1  [N_*D_];
__device__ float g_h1  [N_*D_];
__device__ float g_qkv [N_*3*D_];
__device__ float g_attn[N_*D_];
__device__ float g_h2  [N_*D_];
__device__ float g_ffn [N_*DFF_];

// ---------------- streams/events for branch overlap (created once at load) ---
struct StreamHolder {
  cudaStream_t s2; cudaEvent_t evFork, evJoin;
  StreamHolder(){
    cudaStreamCreateWithFlags(&s2, cudaStreamNonBlocking);
    cudaEventCreateWithFlags(&evFork, cudaEventDisableTiming);
    cudaEventCreateWithFlags(&evJoin, cudaEventDisableTiming);
  }
};
static StreamHolder g_sh;

// ---------------- helpers ----------------------------------------------------
__device__ __forceinline__ unsigned f2tf(float f){
  unsigned r; asm("cvt.rna.tf32.f32 %0, %1;" : "=r"(r) : "f"(f)); return r;
}
__device__ __forceinline__ unsigned bf2(float hi, float lo){
  unsigned r; asm("cvt.rn.bf16x2.f32 %0, %1, %2;" : "=r"(r) : "f"(hi), "f"(lo)); return r;
}
__device__ __forceinline__ void st4tf_pair(unsigned* rowbase, int c4, float4 v){
  int base = ((c4>>3)<<3) + ((c4>>2)&1);
  rowbase[base+0]=f2tf(v.x); rowbase[base+2]=f2tf(v.y);
  rowbase[base+4]=f2tf(v.z); rowbase[base+6]=f2tf(v.w);
}
__device__ __forceinline__ void mma8(float c[4], unsigned a0,unsigned a1,unsigned a2,unsigned a3,
                                     unsigned b0, unsigned b1){
  asm volatile("mma.sync.aligned.m16n8k8.row.col.f32.tf32.tf32.f32 "
      "{%0,%1,%2,%3},{%4,%5,%6,%7},{%8,%9},{%0,%1,%2,%3};"
      : "+f"(c[0]),"+f"(c[1]),"+f"(c[2]),"+f"(c[3])
      : "r"(a0),"r"(a1),"r"(a2),"r"(a3),"r"(b0),"r"(b1));
}
template<int ACT> __device__ __forceinline__ float actf(float x){
  if (ACT==1) return fmaxf(x, 0.f);
  if (ACT==2) return 0.5f*x*(1.f + erff(x*0.70710678118654752f));
  return x;
}

// ---------------- zero init --------------------------------------------------
__global__ void zero_kernel(float4* p, int n){
  int i = blockIdx.x*blockDim.x + threadIdx.x;
  if (i < n) p[i] = make_float4(0.f,0.f,0.f,0.f);
}

// ---------------- fused edge stage v3 (bf16-packed operands) ------------------
#define EDGE_T 4
#define EDGE_SMEM ((4*128*20 + 2*2560)*4 + 512 + 2048)
__global__ void __launch_bounds__(256,2) edge_kernel(
    const float* __restrict__ ea, const float* __restrict__ Wt,
    const float* __restrict__ eb, const float* __restrict__ h,
    const int* __restrict__ src, const int* __restrict__ dst,
    float* __restrict__ agg){
  extern __shared__ unsigned smu[];
  unsigned* Wres = smu;                     // [4][128][20]
  unsigned* Abuf = smu + 4*128*20;          // [2][2560]
  float*    s_eb = (float*)(smu + 4*128*20 + 2*2560);
  int*      sidx = (int*)(s_eb + 128);      // [2][256]
  int tid = threadIdx.x;
  {
    int colW = tid>>1, sW = tid&1;
    #pragma unroll
    for (int ck=0; ck<4; ck++){
      const float* wr = Wt + (size_t)colW*128 + ck*32 + sW*16;
      float4 f0 = *(const float4*)(wr);
      float4 f1 = *(const float4*)(wr+4);
      float4 f2 = *(const float4*)(wr+8);
      float4 f3 = *(const float4*)(wr+12);
      unsigned* d = Wres + ck*2560 + colW*20 + sW*8;
      *(uint4*)(d)   = make_uint4(bf2(f1.x,f0.x), bf2(f1.y,f0.y), bf2(f1.z,f0.z), bf2(f1.w,f0.w));
      *(uint4*)(d+4) = make_uint4(bf2(f3.x,f2.x), bf2(f3.y,f2.y), bf2(f3.z,f2.z), bf2(f3.w,f2.w));
    }
  }
  if (tid < 128) s_eb[tid] = eb[tid];
  int gA = tid>>2, sA = tid&3;
  int r0l = (gA>>3)*16 + (gA&7);
  int r1l = r0l + 8;
  unsigned* Adst0 = Abuf + (gA>>3)*320 + (gA&7)*40 + sA*8;
  {
    int e0 = blockIdx.x*(EDGE_T*128);
    sidx[tid] = (tid<128) ? src[e0+tid] : dst[e0+tid-128];
    const float* p0 = ea + (size_t)(e0+r0l)*128 + sA*8;
    const float* p1 = ea + (size_t)(e0+r1l)*128 + sA*8;
    float4 a0 = *(const float4*)(p0), a1 = *(const float4*)(p0+4);
    float4 a2 = *(const float4*)(p1), a3 = *(const float4*)(p1+4);
    *(uint4*)(Adst0)   = make_uint4(bf2(a2.x,a0.x), bf2(a3.x,a1.x), bf2(a2.y,a0.y), bf2(a3.y,a1.y));
    *(uint4*)(Adst0+4) = make_uint4(bf2(a2.z,a0.z), bf2(a3.z,a1.z), bf2(a2.w,a0.w), bf2(a3.w,a1.w));
  }
  int warp = tid>>5, lane = tid&31, gr = lane>>2, tg = lane&3;
  int wm = warp>>1, wn = warp&1;
  float acc[2][8][4];
  #pragma unroll
  for (int mt=0;mt<2;mt++)
    #pragma unroll
    for (int nt=0;nt<8;nt++){acc[mt][nt][0]=acc[mt][nt][1]=acc[mt][nt][2]=acc[mt][nt][3]=0.f;}
  float4 va[4]; int idxreg = 0;
  const int NIT = EDGE_T*4;
  for (int i = 0; i < NIT; i++){
    __syncthreads();
    int ip = i+1;
    if (ip < NIT){
      int t_ = ip>>2, c_ = ip&3;
      int e0 = blockIdx.x*(EDGE_T*128) + t_*128;
      const float* p0 = ea + (size_t)(e0+r0l)*128 + c_*32 + sA*8;
      const float* p1 = ea + (size_t)(e0+r1l)*128 + c_*32 + sA*8;
      va[0] = *(const float4*)(p0); va[1] = *(const float4*)(p0+4);
      va[2] = *(const float4*)(p1); va[3] = *(const float4*)(p1+4);
      if (c_ == 0) idxreg = (tid<128) ? src[e0+tid] : dst[e0+tid-128];
    }
    const unsigned* Ab = Abuf + (i&1)*2560;
    const unsigned* Wb = Wres + (i&3)*2560;
    #pragma unroll
    for (int ks=0; ks<4; ks++){
      uint2 A0 = *(const uint2*)(Ab + (wm*2+0)*320 + gr*40 + ks*8 + tg*2);
      uint2 A1 = *(const uint2*)(Ab + (wm*2+1)*320 + gr*40 + ks*8 + tg*2);
      unsigned a00 = A0.x<<16, a01 = A0.x&0xFFFF0000u;
      unsigned a02 = A0.y<<16, a03 = A0.y&0xFFFF0000u;
      unsigned a10 = A1.x<<16, a11 = A1.x&0xFFFF0000u;
      unsigned a12 = A1.y<<16, a13 = A1.y&0xFFFF0000u;
      #pragma unroll
      for (int nt=0;nt<8;nt++){
        unsigned bu = Wb[(wn*64+nt*8+gr)*20 + ks*4 + tg];
        unsigned b0 = bu<<16, b1 = bu&0xFFFF0000u;
        mma8(acc[0][nt], a00,a01,a02,a03, b0,b1);
        mma8(acc[1][nt], a10,a11,a12,a13, b0,b1);
      }
    }
    if (ip < NIT){
      unsigned* Ad = Abuf + (ip&1)*2560 + (gA>>3)*320 + (gA&7)*40 + sA*8;
      *(uint4*)(Ad)   = make_uint4(bf2(va[2].x,va[0].x), bf2(va[3].x,va[1].x), bf2(va[2].y,va[0].y), bf2(va[3].y,va[1].y));
      *(uint4*)(Ad+4) = make_uint4(bf2(va[2].z,va[0].z), bf2(va[3].z,va[1].z), bf2(va[2].w,va[0].w), bf2(va[3].w,va[1].w));
      if ((ip&3)==0) sidx[((ip>>2)&1)*256 + tid] = idxreg;
    }
    if ((i&3)==3){
      int tp = ((i>>2)&1)*256;
      #pragma unroll
      for (int mt=0;mt<2;mt++){
        #pragma unroll
        for (int half=0; half<2; half++){
          int r = wm*32 + mt*16 + half*8 + gr;
          int sid = sidx[tp+r], did = sidx[tp+128+r];
          const float* hrow = h   + (size_t)sid*128;
          float*       arow = agg + (size_t)did*128;
          #pragma unroll
          for (int nt=0;nt<8;nt++){
            int col = wn*64 + nt*8 + 2*tg;
            float2 hv = *(const float2*)(hrow + col);
            float v0 = acc[mt][nt][half*2+0] + s_eb[col]   + hv.x;
            float v1 = acc[mt][nt][half*2+1] + s_eb[col+1] + hv.y;
            atomicAdd((float2*)(arow + col), make_float2(fmaxf(v0,0.f), fmaxf(v1,0.f)));
          }
        }
      }
      #pragma unroll
      for (int mt=0;mt<2;mt++)
        #pragma unroll
        for (int nt=0;nt<8;nt++){acc[mt][nt][0]=acc[mt][nt][1]=acc[mt][nt][2]=acc[mt][nt][3]=0.f;}
    }
  }
}

// ---------------- generic tf32 GEMM: C = act(A(+A2)@W^T + bias) --------------
#define GEMM_SMEM ((2*64*36 + 2*128*36)*4)
template<int ACT, bool HASA2, bool GATHER, int LNM>
__global__ void __launch_bounds__(128,3) gemm_kernel(
    const float* __restrict__ A, const float* __restrict__ A2,
    const int* __restrict__ gidx, const float* __restrict__ W,
    const float* __restrict__ bias, float* __restrict__ C,
    int K, int Nout,
    const float* __restrict__ Rres, const int* __restrict__ midx,
    const float* __restrict__ lnw, const float* __restrict__ lnb){
  extern __shared__ float sm[];
  unsigned* Asm = (unsigned*)sm;             // [2][64*36]
  unsigned* Wsm = (unsigned*)(sm + 2*64*36); // [2][128*36]
  int tid = threadIdx.x, warp = tid>>5, lane = tid&31, gr = lane>>2, tg = lane&3;
  int wm = warp>>1, wn = warp&1;
  int m0 = blockIdx.y*64, n0 = blockIdx.x*128;
  int c4 = (tid&7)<<2;
  int abase = ((c4>>3)<<3) + ((c4>>2)&1);
  int lrow[4], arow[4], wrow[8];
  #pragma unroll
  for (int it=0; it<4; it++){
    int r = (tid + it*128)>>3;
    lrow[it] = m0 + r;
    arow[it] = GATHER ? gidx[m0+r] : (m0+r);
  }
  #pragma unroll
  for (int it=0; it<8; it++) wrow[it] = n0 + ((tid + it*128)>>3);

  float4 va[4], vw[8];
  #pragma unroll
  for (int it=0; it<4; it++){
    va[it] = *(const float4*)(A + (size_t)arow[it]*K + c4);
    if (HASA2){
      float4 u = *(const float4*)(A2 + (size_t)lrow[it]*K + c4);
      va[it].x+=u.x; va[it].y+=u.y; va[it].z+=u.z; va[it].w+=u.w;
    }
  }
  #pragma unroll
  for (int it=0; it<8; it++) vw[it] = *(const float4*)(W + (size_t)wrow[it]*K + c4);
  #pragma unroll
  for (int it=0; it<4; it++){
    unsigned* d = Asm + ((tid+it*128)>>3)*36 + abase;
    d[0]=f2tf(va[it].x); d[2]=f2tf(va[it].y); d[4]=f2tf(va[it].z); d[6]=f2tf(va[it].w);
  }
  #pragma unroll
  for (int it=0; it<8; it++){
    unsigned* d = Wsm + ((tid+it*128)>>3)*36 + abase;
    d[0]=f2tf(vw[it].x); d[2]=f2tf(vw[it].y); d[4]=f2tf(vw[it].z); d[6]=f2tf(vw[it].w);
  }

  float acc[2][8][4];
  #pragma unroll
  for (int mt=0;mt<2;mt++)
    #pragma unroll
    for (int nt=0;nt<8;nt++){acc[mt][nt][0]=acc[mt][nt][1]=acc[mt][nt][2]=acc[mt][nt][3]=0.f;}

  int nc = K >> 5;
  for (int c = 0; c < nc; c++){
    __syncthreads();
    if (c+1 < nc){
      int k0 = (c+1)<<5;
      #pragma unroll
      for (int it=0; it<4; it++){
        va[it] = *(const float4*)(A + (size_t)arow[it]*K + k0 + c4);
        if (HASA2){
          float4 u = *(const float4*)(A2 + (size_t)lrow[it]*K + k0 + c4);
          va[it].x+=u.x; va[it].y+=u.y; va[it].z+=u.z; va[it].w+=u.w;
        }
      }
      #pragma unroll
      for (int it=0; it<8; it++) vw[it] = *(const float4*)(W + (size_t)wrow[it]*K + k0 + c4);
    }
    const unsigned* Ab = Asm + (c&1)*64*36;
    const unsigned* Wb = Wsm + (c&1)*128*36;
    #pragma unroll
    for (int ks=0; ks<4; ks++){
      uint2 alo0 = *(const uint2*)(Ab + (wm*32+   gr)*36 + ks*8 + tg*2);
      uint2 ahi0 = *(const uint2*)(Ab + (wm*32+ 8+gr)*36 + ks*8 + tg*2);
      uint2 alo1 = *(const uint2*)(Ab + (wm*32+16+gr)*36 + ks*8 + tg*2);
      uint2 ahi1 = *(const uint2*)(Ab + (wm*32+24+gr)*36 + ks*8 + tg*2);
      #pragma unroll
      for (int nt=0;nt<8;nt++){
        uint2 bb = *(const uint2*)(Wb + (wn*64+nt*8+gr)*36 + ks*8 + tg*2);
        mma8(acc[0][nt], alo0.x, ahi0.x, alo0.y, ahi0.y, bb.x, bb.y);
        mma8(acc[1][nt], alo1.x, ahi1.x, alo1.y, ahi1.y, bb.x, bb.y);
      }
    }
    if (c+1 < nc){
      unsigned* Ad = Asm + ((c+1)&1)*64*36;
      unsigned* Wd = Wsm + ((c+1)&1)*128*36;
      #pragma unroll
      for (int it=0; it<4; it++){
        unsigned* d = Ad + ((tid+it*128)>>3)*36 + abase;
        d[0]=f2tf(va[it].x); d[2]=f2tf(va[it].y); d[4]=f2tf(va[it].z); d[6]=f2tf(va[it].w);
      }
      #pragma unroll
      for (int it=0; it<8; it++){
        unsigned* d = Wd + ((tid+it*128)>>3)*36 + abase;
        d[0]=f2tf(vw[it].x); d[2]=f2tf(vw[it].y); d[4]=f2tf(vw[it].z); d[6]=f2tf(vw[it].w);
      }
    }
  }

  if (LNM == 0){
    #pragma unroll
    for (int mt=0;mt<2;mt++){
      #pragma unroll
      for (int nt=0;nt<8;nt++){
        int row = m0 + wm*32 + mt*16 + gr;
        int col = n0 + wn*64 + nt*8 + 2*tg;
        float2 bv = *(const float2*)(bias + col);
        float v00 = actf<ACT>(acc[mt][nt][0] + bv.x);
        float v01 = actf<ACT>(acc[mt][nt][1] + bv.y);
        float v10 = actf<ACT>(acc[mt][nt][2] + bv.x);
        float v11 = actf<ACT>(acc[mt][nt][3] + bv.y);
        *(float2*)(C + (size_t)row*Nout + col)     = make_float2(v00, v01);
        *(float2*)(C + (size_t)(row+8)*Nout + col) = make_float2(v10, v11);
      }
    }
  } else {
    __syncthreads();
    float2* red = (float2*)sm;   // [64][2]
    int orows[2][2];
    #pragma unroll
    for (int mt=0;mt<2;mt++){
      #pragma unroll
      for (int half=0; half<2; half++){
        int rl_ = wm*32 + mt*16 + half*8 + gr;
        int row = m0 + rl_;
        int orow = (LNM==2) ? midx[row] : row;
        orows[mt][half] = orow;
        const float* R = Rres + (size_t)orow*128;
        float s = 0.f, q = 0.f;
        #pragma unroll
        for (int nt=0;nt<8;nt++){
          int col = wn*64 + nt*8 + 2*tg;
          float2 bv = *(const float2*)(bias + col);
          float2 rv = *(const float2*)(R + col);
          float v0 = acc[mt][nt][half*2+0] + bv.x + rv.x;
          float v1 = acc[mt][nt][half*2+1] + bv.y + rv.y;
          acc[mt][nt][half*2+0] = v0; acc[mt][nt][half*2+1] = v1;
          s += v0 + v1; q += v0*v0 + v1*v1;
        }
        s += __shfl_xor_sync(0xffffffffu, s, 1); q += __shfl_xor_sync(0xffffffffu, q, 1);
        s += __shfl_xor_sync(0xffffffffu, s, 2); q += __shfl_xor_sync(0xffffffffu, q, 2);
        if (tg == 0) red[rl_*2 + wn] = make_float2(s, q);
      }
    }
    __syncthreads();
    #pragma unroll
    for (int mt=0;mt<2;mt++){
      #pragma unroll
      for (int half=0; half<2; half++){
        int rl_ = wm*32 + mt*16 + half*8 + gr;
        float2 p0 = red[rl_*2], p1 = red[rl_*2+1];
        float S = p0.x + p1.x, Q = p0.y + p1.y;
        float mu = S*(1.f/128.f);
        float var = Q*(1.f/128.f) - mu*mu;
        float rs = rsqrtf(var + 1e-5f);
        float* Co = C + (size_t)orows[mt][half]*128;
        #pragma unroll
        for (int nt=0;nt<8;nt++){
          int col = wn*64 + nt*8 + 2*tg;
          float2 wv = *(const float2*)(lnw + col);
          float2 bv = *(const float2*)(lnb + col);
          float o0 = (acc[mt][nt][half*2+0]-mu)*rs*wv.x + bv.x;
          float o1 = (acc[mt][nt][half*2+1]-mu)*rs*wv.y + bv.y;
          *(float2*)(Co + col) = make_float2(o0, o1);
        }
      }
    }
  }
}

// ---------------- flash attention v3 (bf16-packed Q/K/V/P) --------------------
// K-tile 64, double-buffered K/V, 36KB smem, 2 CTAs/SM + co-residency.
// Qp [64][24] row-pair bf16; Kp [2][64][12] k-pair bf16; Vp [2][32][24] kvrow-
// pair bf16; Pp [64][72] row-pair bf16. tf32 mma via <<16 / &0xFFFF0000 unpack.
#define ATTN_SMEM (9216*4)
__global__ void __launch_bounds__(256,2) attn_kernel(const float* __restrict__ qkv,
                                                     float* __restrict__ outp){
  extern __shared__ unsigned smq[];
  unsigned* Qp = smq;          // [64][24]
  unsigned* Kp = smq + 1536;   // [2][64][12]
  unsigned* Vp = smq + 3072;   // [2][32][24]
  unsigned* Pp = smq + 4608;   // [64][72]
  int tid = threadIdx.x, warp = tid>>5, lane = tid&31, gr = lane>>2, tg = lane&3;
  int qt = blockIdx.x, bh = blockIdx.y;
  int b = bh>>3, hh = bh&7;
  int qrow0 = b*SEQ_ + qt*128;

  // ---- Q load: row-pair bf16, scaled by 1/sqrt(hd)=0.25 ----
  {
    int line = tid>>2, kq = tid&3;
    int r0 = (line>>3)*16 + (line&7);
    const float* q0 = qkv + (size_t)(qrow0+r0)*384 + hh*16 + kq*4;
    float4 f0 = *(const float4*)(q0);
    float4 f1 = *(const float4*)(q0 + 8*384);
    const float* a0 = (const float*)&f0;
    const float* a1 = (const float*)&f1;
    #pragma unroll
    for (int i=0;i<4;i++){
      int k = kq*4+i;
      int pos = (k>>3)*8 + ((k&7)&3)*2 + ((k&7)>>2);
      Qp[line*24 + pos] = bf2(a1[i]*0.25f, a0[i]*0.25f);
    }
  }
  // loader coords
  int krow = tid>>2, kq2 = tid&3;
  int kg = kq2>>1, klp = (kq2&1)*2;
  int vp_ = tid>>3, vcq = tid&7;
  int vr0 = (vp_>>2)*8 + (vp_&3);
  // ---- prologue: KV tile 0 into buffer 0 ----
  {
    const float* kbase = qkv + (size_t)(b*SEQ_ + krow)*384 + 128 + hh*16;
    float2 ka = *(const float2*)(kbase + kg*8 + klp);
    float2 kb = *(const float2*)(kbase + kg*8 + klp + 4);
    *(uint2*)(Kp + krow*12 + kg*4 + klp) = make_uint2(bf2(kb.x, ka.x), bf2(kb.y, ka.y));
    const float* vbase = qkv + (size_t)(b*SEQ_ + vr0)*384 + 256 + hh*16;
    float2 v0 = *(const float2*)(vbase + vcq*2);
    float2 v1 = *(const float2*)(vbase + 4*384 + vcq*2);
    *(uint2*)(Vp + vp_*24 + vcq*2) = make_uint2(bf2(v1.x, v0.x), bf2(v1.y, v0.y));
  }
  int m0 = warp*16;
  int prl = (warp*8 + gr);
  int p0 = ((2*tg)&3)*2 + (tg>>1);
  int p1 = ((2*tg+1)&3)*2 + ((2*tg+1)>>2);
  float mrow0 = -1e30f, mrow1 = -1e30f, lrow0 = 0.f, lrow1 = 0.f;
  float o[2][4];
  #pragma unroll
  for (int nt=0;nt<2;nt++){o[nt][0]=o[nt][1]=o[nt][2]=o[nt][3]=0.f;}

  for (int kt = 0; kt < 16; kt++){
    __syncthreads();
    float2 ka, kb, v0, v1;
    if (kt+1 < 16){
      const float* kbase = qkv + (size_t)(b*SEQ_ + (kt+1)*64 + krow)*384 + 128 + hh*16;
      ka = *(const float2*)(kbase + kg*8 + klp);
      kb = *(const float2*)(kbase + kg*8 + klp + 4);
      const float* vbase = qkv + (size_t)(b*SEQ_ + (kt+1)*64 + vr0)*384 + 256 + hh*16;
      v0 = *(const float2*)(vbase + vcq*2);
      v1 = *(const float2*)(vbase + 4*384 + vcq*2);
    }
    const unsigned* Kb = Kp + (kt&1)*768;
    const unsigned* Vb = Vp + (kt&1)*768;
    float s[8][4];
    #pragma unroll
    for (int j=0;j<8;j++){s[j][0]=s[j][1]=s[j][2]=s[j][3]=0.f;}
    #pragma unroll
    for (int ks=0; ks<2; ks++){
      uint2 qa = *(const uint2*)(Qp + prl*24 + ks*8 + tg*2);
      unsigned a0 = qa.x<<16, a1 = qa.x&0xFFFF0000u;
      unsigned a2 = qa.y<<16, a3 = qa.y&0xFFFF0000u;
      #pragma unroll
      for (int j=0;j<8;j++){
        unsigned bu = Kb[(j*8+gr)*12 + ks*4 + tg];
        mma8(s[j], a0,a1,a2,a3, bu<<16, bu&0xFFFF0000u);
      }
    }
    // online softmax: rows gr (comps 0,1) and gr+8 (comps 2,3)
    float mx0 = -1e30f, mx1 = -1e30f;
    #pragma unroll
    for (int j=0;j<8;j++){
      mx0 = fmaxf(mx0, fmaxf(s[j][0], s[j][1]));
      mx1 = fmaxf(mx1, fmaxf(s[j][2], s[j][3]));
    }
    mx0 = fmaxf(mx0, __shfl_xor_sync(0xffffffffu, mx0, 1));
    mx0 = fmaxf(mx0, __shfl_xor_sync(0xffffffffu, mx0, 2));
    mx1 = fmaxf(mx1, __shfl_xor_sync(0xffffffffu, mx1, 1));
    mx1 = fmaxf(mx1, __shfl_xor_sync(0xffffffffu, mx1, 2));
    float mn0 = fmaxf(mrow0, mx0), mn1 = fmaxf(mrow1, mx1);
    float al0 = __expf(mrow0 - mn0), al1 = __expf(mrow1 - mn1);
    mrow0 = mn0; mrow1 = mn1;
    float ls0 = 0.f, ls1 = 0.f;
    #pragma unroll
    for (int j=0;j<8;j++){
      s[j][0] = __expf(s[j][0]-mn0); s[j][1] = __expf(s[j][1]-mn0);
      s[j][2] = __expf(s[j][2]-mn1); s[j][3] = __expf(s[j][3]-mn1);
      ls0 += s[j][0]+s[j][1]; ls1 += s[j][2]+s[j][3];
    }
    ls0 += __shfl_xor_sync(0xffffffffu, ls0, 1); ls0 += __shfl_xor_sync(0xffffffffu, ls0, 2);
    ls1 += __shfl_xor_sync(0xffffffffu, ls1, 1); ls1 += __shfl_xor_sync(0xffffffffu, ls1, 2);
    lrow0 = lrow0*al0 + ls0; lrow1 = lrow1*al1 + ls1;
    #pragma unroll
    for (int nt=0;nt<2;nt++){ o[nt][0]*=al0; o[nt][1]*=al0; o[nt][2]*=al1; o[nt][3]*=al1; }
    // P store: row-pair bf16 {lo=row gr, hi=row gr+8}
    #pragma unroll
    for (int j=0;j<8;j++){
      Pp[prl*72 + j*8 + p0] = bf2(s[j][2], s[j][0]);
      Pp[prl*72 + j*8 + p1] = bf2(s[j][3], s[j][1]);
    }
    __syncwarp();
    #pragma unroll
    for (int ks=0; ks<8; ks++){
      uint2 pa = *(const uint2*)(Pp + prl*72 + ks*8 + tg*2);
      unsigned a0 = pa.x<<16, a1 = pa.x&0xFFFF0000u;
      unsigned a2 = pa.y<<16, a3 = pa.y&0xFFFF0000u;
      #pragma unroll
      for (int nt=0; nt<2; nt++){
        unsigned vu = Vb[(ks*4+tg)*24 + nt*8 + gr];
        mma8(o[nt], a0,a1,a2,a3, vu<<16, vu&0xFFFF0000u);
      }
    }
    if (kt+1 < 16){
      *(uint2*)(Kp + ((kt+1)&1)*768 + krow*12 + kg*4 + klp) =
          make_uint2(bf2(kb.x, ka.x), bf2(kb.y, ka.y));
      *(uint2*)(Vp + ((kt+1)&1)*768 + vp_*24 + vcq*2) =
          make_uint2(bf2(v1.x, v0.x), bf2(v1.y, v0.y));
    }
  }
  float inv0 = 1.f/lrow0, inv1 = 1.f/lrow1;
  #pragma unroll
  for (int nt=0; nt<2; nt++){
    int col = hh*16 + nt*8 + 2*tg;
    size_t r0 = (size_t)(qrow0 + m0 + gr    )*128 + col;
    size_t r1 = (size_t)(qrow0 + m0 + gr + 8)*128 + col;
    *(float2*)(outp + r0) = make_float2(o[nt][0]*inv0, o[nt][1]*inv0);
    *(float2*)(outp + r1) = make_float2(o[nt][2]*inv1, o[nt][3]*inv1);
  }
}

// ---------------- launch ------------------------------------------------------
extern "C" void kernel_launch(void* const* d_in, const int* in_sizes, int n_in,
                              void* d_out, int out_size){
  const float* h         = (const float*)d_in[0];
  const float* edge_attr = (const float*)d_in[1];
  const float* edge_w    = (const float*)d_in[2];
  const float* edge_b    = (const float*)d_in[3];
  const float* gin_w1    = (const float*)d_in[4];
  const float* gin_b1    = (const float*)d_in[5];
  const float* gin_w2    = (const float*)d_in[6];
  const float* gin_b2    = (const float*)d_in[7];
  const float* in_proj_w = (const float*)d_in[8];
  const float* in_proj_b = (const float*)d_in[9];
  const float* out_w     = (const float*)d_in[10];
  const float* out_b     = (const float*)d_in[11];
  const float* ffn_w1    = (const float*)d_in[12];
  const float* ffn_b1    = (const float*)d_in[13];
  const float* ffn_w2    = (const float*)d_in[14];
  const float* ffn_b2    = (const float*)d_in[15];
  const float* ln1_w     = (const float*)d_in[16];
  const float* ln1_b     = (const float*)d_in[17];
  const float* ln2_w     = (const float*)d_in[18];
  const float* ln2_b     = (const float*)d_in[19];
  const float* ln3_w     = (const float*)d_in[20];
  const float* ln3_b     = (const float*)d_in[21];
  const int*   edge_index= (const int*)d_in[22];
  const int*   sort_idx  = (const int*)d_in[24];
  float* outp = (float*)d_out;

  float *agg,*t1,*h1b,*qkvb,*attnb,*h2b,*ffnb;
  cudaGetSymbolAddress((void**)&agg,  g_agg);
  cudaGetSymbolAddress((void**)&t1,   g_t1);
  cudaGetSymbolAddress((void**)&h1b,  g_h1);
  cudaGetSymbolAddress((void**)&qkvb, g_qkv);
  cudaGetSymbolAddress((void**)&attnb,g_attn);
  cudaGetSymbolAddress((void**)&h2b,  g_h2);
  cudaGetSymbolAddress((void**)&ffnb, g_ffn);

  cudaFuncSetAttribute(edge_kernel, cudaFuncAttributeMaxDynamicSharedMemorySize, EDGE_SMEM);
  cudaFuncSetAttribute(gemm_kernel<1,true ,false,0>, cudaFuncAttributeMaxDynamicSharedMemorySize, GEMM_SMEM);
  cudaFuncSetAttribute(gemm_kernel<0,false,false,1>, cudaFuncAttributeMaxDynamicSharedMemorySize, GEMM_SMEM);
  cudaFuncSetAttribute(gemm_kernel<0,false,true ,0>, cudaFuncAttributeMaxDynamicSharedMemorySize, GEMM_SMEM);
  cudaFuncSetAttribute(gemm_kernel<0,false,false,2>, cudaFuncAttributeMaxDynamicSharedMemorySize, GEMM_SMEM);
  cudaFuncSetAttribute(gemm_kernel<2,false,false,0>, cudaFuncAttributeMaxDynamicSharedMemorySize, GEMM_SMEM);
  cudaFuncSetAttribute(attn_kernel, cudaFuncAttributeMaxDynamicSharedMemorySize, ATTN_SMEM);

  // fork point recorded at graph start (s2 branch depends on nothing)
  cudaEventRecord(g_sh.evFork, 0);
  cudaStreamWaitEvent(g_sh.s2, g_sh.evFork, 0);

  // ---- local branch FIRST in creation order (edge gets SM priority) ----
  zero_kernel<<<(N_*D_/4 + 255)/256, 256>>>((float4*)agg, N_*D_/4);
  edge_kernel<<<E_/(EDGE_T*128), 256, EDGE_SMEM>>>(edge_attr, edge_w, edge_b, h,
                                                   edge_index, edge_index + E_, agg);
  gemm_kernel<1,true ,false,0><<<dim3(1,N_/64),128,GEMM_SMEM>>>(h,  agg,    nullptr, gin_w1, gin_b1, t1,  128, 128, nullptr, nullptr, nullptr, nullptr);
  gemm_kernel<0,false,false,1><<<dim3(1,N_/64),128,GEMM_SMEM>>>(t1, nullptr,nullptr, gin_w2, gin_b2, h1b, 128, 128, h, nullptr, ln1_w, ln1_b);

  // ---- global branch (qkv -> attention) on side stream s2 ----
  gemm_kernel<0,false,true ,0><<<dim3(3,N_/64),128,GEMM_SMEM,g_sh.s2>>>(
      h, nullptr, sort_idx, in_proj_w, in_proj_b, qkvb, 128, 384,
      nullptr, nullptr, nullptr, nullptr);
  attn_kernel<<<dim3(8,128),256,ATTN_SMEM,g_sh.s2>>>(qkvb, attnb);
  cudaEventRecord(g_sh.evJoin, g_sh.s2);

  // ---- join: out projection + LN2 (needs h1b and attnb) ----
  cudaStreamWaitEvent(0, g_sh.evJoin, 0);
  gemm_kernel<0,false,false,2><<<dim3(1,N_/64),128,GEMM_SMEM>>>(attnb, nullptr,nullptr, out_w, out_b, h2b, 128, 128, h1b, sort_idx, ln2_w, ln2_b);
  // ---- FFN: gelu gemm, then ffn2 + fused LN3 -> final output ----
  gemm_kernel<2,false,false,0><<<dim3(4,N_/64),128,GEMM_SMEM>>>(h2b, nullptr,nullptr, ffn_w1, ffn_b1, ffnb, 128, 512, nullptr, nullptr, nullptr, nullptr);
  gemm_kernel<0,false,false,1><<<dim3(1,N_/64),128,GEMM_SMEM>>>(ffnb,nullptr,nullptr, ffn_w2, ffn_b2, outp, 512, 128, h2b, nullptr, ln3_w, ln3_b);
}